// round 4
// baseline (speedup 1.0000x reference)
#include <cuda_runtime.h>
#include <cuda_bf16.h>
#include <math.h>

#define NNODES 50000
#define NEDGES 500000
#define ETOT   (NEDGES + NNODES)   // with self loops
#define INF    128
#define HID    64
#define HEADS  4
#define ZW     (HEADS * HID)       // 256
#define NG     16
#define OUTF   326000

// ---------------- scratch (device globals; no allocation allowed) ----------
__device__ float  g_h[2 * NNODES * HID];    // ping-pong node features (flat)
__device__ float4 g_z[NNODES * (ZW / 4)];   // projected features, 16B aligned
__device__ float  g_als[NNODES * HEADS];
__device__ float  g_ald[NNODES * HEADS];
__device__ int    g_deg[NNODES];
__device__ int    g_off[NNODES + 1];
__device__ int    g_cur[NNODES];
__device__ int    g_csr[ETOT];              // src indices grouped by dst
__device__ float  g_hg[NG * HID];           // pooled graph features

// ---------------- CSR build -------------------------------------------------
// Self-loops handled analytically: every node starts with degree 1 and its
// self-loop is pre-placed at slot g_off[i] during the scan.
__global__ void k_init_deg() {
    int i = blockIdx.x * blockDim.x + threadIdx.x;
    if (i < NNODES) g_deg[i] = 1;
}

// edge_index / batch are int32 (JAX default x64-disabled)
__global__ void k_count(const int* __restrict__ ei) {
    int e = blockIdx.x * blockDim.x + threadIdx.x;
    if (e >= NEDGES) return;
    int d = ei[NEDGES + e];
    atomicAdd(&g_deg[d], 1);
}

__global__ void k_scan() {
    __shared__ int sm[2048];      // padded: reads always in-bounds
    int t = threadIdx.x;          // 1024 threads
    const int CH = (NNODES + 1023) / 1024;
    int lo = t * CH;
    int hi = min(lo + CH, NNODES);
    int s = 0;
    for (int i = lo; i < hi; i++) s += g_deg[i];
    sm[t] = 0;
    sm[1024 + t] = s;
    __syncthreads();
    for (int d = 1; d < 1024; d <<= 1) {
        int v = sm[1024 + t - d]; // in-bounds for all t, all d
        __syncthreads();
        sm[1024 + t] += v;
        __syncthreads();
    }
    int run = sm[1023 + t];       // exclusive prefix (sm[1023] == 0 pad)
    for (int i = lo; i < hi; i++) {
        g_off[i] = run;
        g_csr[run] = i;           // self-loop at first slot
        g_cur[i] = run + 1;
        run += g_deg[i];
    }
    if (t == 1023) g_off[NNODES] = sm[2047];
}

__global__ void k_scatter(const int* __restrict__ ei) {
    int e = blockIdx.x * blockDim.x + threadIdx.x;
    if (e >= NEDGES) return;
    int s = ei[e];
    int d = ei[NEDGES + e];
    int p = atomicAdd(&g_cur[d], 1);
    g_csr[p] = s;
}

// ---------------- embedding: h0 = x @ W_emb + b -----------------------------
__global__ void k_emb(const float* __restrict__ x,
                      const float* __restrict__ W,
                      const float* __restrict__ b) {
    __shared__ float xs[INF];
    int n = blockIdx.x;
    int t = threadIdx.x;          // 128 threads
    xs[t] = x[n * INF + t];
    __syncthreads();
    if (t < HID) {                // warp-uniform guard (warps 0,1)
        float acc = b[t];
        #pragma unroll
        for (int f = 0; f < INF; f++) acc = fmaf(xs[f], W[f * HID + t], acc);
        g_h[n * HID + t] = acc;
    }
}

// ---------------- z = h @ W  and attention logits ---------------------------
__global__ void k_z(const float* __restrict__ Wg,
                    const float* __restrict__ asrc,
                    const float* __restrict__ adst,
                    int cur) {
    __shared__ float hs[HID];
    __shared__ float red[32];
    int n = blockIdx.x;
    int k = threadIdx.x;          // 256 threads
    const float* h = g_h + (size_t)cur * NNODES * HID;
    if (k < HID) hs[k] = h[n * HID + k];
    __syncthreads();
    float acc = 0.f;
    #pragma unroll
    for (int f = 0; f < HID; f++) acc = fmaf(hs[f], Wg[f * ZW + k], acc);
    ((float*)g_z)[n * ZW + k] = acc;

    float ps = acc * asrc[k];
    float pd = acc * adst[k];
    #pragma unroll
    for (int o = 16; o; o >>= 1) {
        ps += __shfl_down_sync(0xffffffffu, ps, o);
        pd += __shfl_down_sync(0xffffffffu, pd, o);
    }
    int w = k >> 5, lane = k & 31;
    if (lane == 0) { red[w * 2] = ps; red[w * 2 + 1] = pd; }
    __syncthreads();
    // masked index: in-bounds for EVERY thread even if loads get speculated
    int kk = k & 3;
    float v0 = red[4 * kk],     v2 = red[4 * kk + 2];
    float v1 = red[4 * kk + 1], v3 = red[4 * kk + 3];
    if (k < HEADS) {
        g_als[n * HEADS + k] = v0 + v2;
        g_ald[n * HEADS + k] = v1 + v3;
    }
}

// ---------------- per-dst aggregation (one warp per node) -------------------
__global__ void k_agg(const float* __restrict__ bg, int cur) {
    int wid = (blockIdx.x * blockDim.x + threadIdx.x) >> 5;
    if (wid >= NNODES) return;
    int n = wid;
    int lane = threadIdx.x & 31;
    int hh = lane >> 3;           // head id (0..3)
    int fg = lane & 7;            // feature group (8 floats = 2 float4)

    float ald = g_ald[n * HEADS + hh];
    float a0=0,a1=0,a2=0,a3=0,a4=0,a5=0,a6=0,a7=0;
    float dsum = 0.f;

    int beg = g_off[n], end = g_off[n + 1];
    int zoff = hh * 16 + fg * 2;  // in float4 units within a node's 64 float4s
    for (int i = beg; i < end; i++) {
        int s = g_csr[i];
        float e = g_als[s * HEADS + hh] + ald;
        e = (e > 0.f) ? e : 0.2f * e;          // leaky relu
        float w = __expf(e);
        dsum += w;
        float4 va = g_z[s * (ZW / 4) + zoff];
        float4 vb = g_z[s * (ZW / 4) + zoff + 1];
        a0 = fmaf(w, va.x, a0); a1 = fmaf(w, va.y, a1);
        a2 = fmaf(w, va.z, a2); a3 = fmaf(w, va.w, a3);
        a4 = fmaf(w, vb.x, a4); a5 = fmaf(w, vb.y, a5);
        a6 = fmaf(w, vb.z, a6); a7 = fmaf(w, vb.w, a7);
    }
    float inv = 1.f / (dsum + 1e-16f);
    a0*=inv; a1*=inv; a2*=inv; a3*=inv; a4*=inv; a5*=inv; a6*=inv; a7*=inv;

    // sum across the 4 heads (lanes L, L^8, L^16, L^24)
    #pragma unroll
    for (int m = 8; m <= 16; m <<= 1) {
        a0 += __shfl_xor_sync(0xffffffffu, a0, m);
        a1 += __shfl_xor_sync(0xffffffffu, a1, m);
        a2 += __shfl_xor_sync(0xffffffffu, a2, m);
        a3 += __shfl_xor_sync(0xffffffffu, a3, m);
        a4 += __shfl_xor_sync(0xffffffffu, a4, m);
        a5 += __shfl_xor_sync(0xffffffffu, a5, m);
        a6 += __shfl_xor_sync(0xffffffffu, a6, m);
        a7 += __shfl_xor_sync(0xffffffffu, a7, m);
    }
    if (hh == 0) {
        int fb = fg * 8;
        float* o = g_h + (size_t)(cur ^ 1) * NNODES * HID + n * HID + fb;
        o[0] = fmaxf(0.25f * a0 + bg[fb + 0], 0.f);
        o[1] = fmaxf(0.25f * a1 + bg[fb + 1], 0.f);
        o[2] = fmaxf(0.25f * a2 + bg[fb + 2], 0.f);
        o[3] = fmaxf(0.25f * a3 + bg[fb + 3], 0.f);
        o[4] = fmaxf(0.25f * a4 + bg[fb + 4], 0.f);
        o[5] = fmaxf(0.25f * a5 + bg[fb + 5], 0.f);
        o[6] = fmaxf(0.25f * a6 + bg[fb + 6], 0.f);
        o[7] = fmaxf(0.25f * a7 + bg[fb + 7], 0.f);
    }
}

// ---------------- global mean pool (batch is sorted int32) -------------------
__global__ void k_pool(const int* __restrict__ batch, int cur) {
    __shared__ int s_lo, s_hi;
    __shared__ float red[256];
    int g = blockIdx.x;
    if (threadIdx.x == 0) {
        int lo = 0, hi = NNODES;
        while (lo < hi) { int m = (lo + hi) >> 1; if (batch[m] < g) lo = m + 1; else hi = m; }
        s_lo = lo;
        lo = 0; hi = NNODES;
        while (lo < hi) { int m = (lo + hi) >> 1; if (batch[m] < g + 1) lo = m + 1; else hi = m; }
        s_hi = lo;
    }
    __syncthreads();
    int lo = s_lo, hi = s_hi;
    int f = threadIdx.x & 63, r = threadIdx.x >> 6;
    const float* h = g_h + (size_t)cur * NNODES * HID;
    float acc = 0.f;
    for (int n = lo + r; n < hi; n += 4) acc += h[n * HID + f];
    red[threadIdx.x] = acc;
    __syncthreads();
    if (threadIdx.x < 64) {       // warp-uniform guard
        float v = red[f] + red[64 + f] + red[128 + f] + red[192 + f];
        float cnt = (float)max(hi - lo, 1);
        g_hg[g * HID + f] = v / cnt;
    }
}

// ---------------- final FC: out[g,o] = hg[g,:] @ W_fc[:,o] + b_fc[o] ---------
__global__ void k_fc(const float* __restrict__ Wfc,
                     const float* __restrict__ bfc,
                     float* __restrict__ out) {
    __shared__ float hg[NG * HID];
    int t = threadIdx.x;          // 256
    for (int i = t; i < NG * HID; i += 256) hg[i] = g_hg[i];
    __syncthreads();
    int o = blockIdx.x * 256 + t;
    if (o >= OUTF) return;
    float bo = bfc[o];
    float acc[NG];
    #pragma unroll
    for (int g = 0; g < NG; g++) acc[g] = bo;
    for (int f = 0; f < HID; f++) {
        float w = Wfc[f * OUTF + o];
        #pragma unroll
        for (int g = 0; g < NG; g++) acc[g] = fmaf(hg[g * HID + f], w, acc[g]);
    }
    #pragma unroll
    for (int g = 0; g < NG; g++) out[(long long)g * OUTF + o] = acc[g];
}

// ---------------- launch ------------------------------------------------------
extern "C" void kernel_launch(void* const* d_in, const int* in_sizes, int n_in,
                              void* d_out, int out_size) {
    const float* x     = (const float*)d_in[0];
    const int*   ei    = (const int*)d_in[1];    // int32 (JAX x64 disabled)
    // d_in[2] edge_attr: unused (matches reference)
    const int*   batch = (const int*)d_in[3];    // int32
    const float* W_emb = (const float*)d_in[4];
    const float* b_emb = (const float*)d_in[5];
    const float* W_gat = (const float*)d_in[6];
    const float* a_src = (const float*)d_in[7];
    const float* a_dst = (const float*)d_in[8];
    const float* b_gat = (const float*)d_in[9];
    const float* W_fc  = (const float*)d_in[10];
    const float* b_fc  = (const float*)d_in[11];
    float* out = (float*)d_out;

    k_init_deg<<<(NNODES + 255) / 256, 256>>>();
    k_count<<<(NEDGES + 255) / 256, 256>>>(ei);
    k_scan<<<1, 1024>>>();
    k_scatter<<<(NEDGES + 255) / 256, 256>>>(ei);
    k_emb<<<NNODES, 128>>>(x, W_emb, b_emb);

    int cur = 0;
    for (int l = 0; l < 3; l++) {
        k_z<<<NNODES, 256>>>(W_gat + (size_t)l * HID * ZW,
                             a_src + (size_t)l * HEADS * HID,
                             a_dst + (size_t)l * HEADS * HID, cur);
        k_agg<<<(NNODES * 32 + 255) / 256, 256>>>(b_gat + (size_t)l * HID, cur);
        cur ^= 1;
    }

    k_pool<<<NG, 256>>>(batch, cur);
    k_fc<<<(OUTF + 255) / 256, 256>>>(W_fc, b_fc, out);
}

// round 5
// speedup vs baseline: 1.5880x; 1.5880x over previous
#include <cuda_runtime.h>
#include <cuda_bf16.h>
#include <math.h>

#define NNODES 50000
#define NEDGES 500000
#define ETOT   (NEDGES + NNODES)
#define INF    128
#define HID    64
#define HEADS  4
#define ZW     (HEADS * HID)       // 256
#define NG     16
#define OUTF   326000
#define NT     32                  // node tile
#define NPAD   50016               // ceil(NNODES/NT)*NT
#define NTILES (NPAD / NT)         // 1563
#define NBLK   196                 // ceil(NNODES/256)

// ---------------- scratch ----------------------------------------------------
__device__ float  g_h[2 * NPAD * HID];      // ping-pong node features
__device__ float4 g_z[NPAD * (ZW / 4)];     // projected features
__device__ float  g_als[NNODES * HEADS];
__device__ float  g_ald[NNODES * HEADS];
__device__ int    g_deg[NNODES];
__device__ int    g_off[NNODES + 1];
__device__ int    g_cur[NNODES];
__device__ int    g_csr[ETOT];
__device__ int    g_bsum[256];
__device__ int    g_boff[256];
__device__ float  g_hg[NG * HID];

// ---------------- CSR build --------------------------------------------------
__global__ void k_init_deg() {
    int i = blockIdx.x * blockDim.x + threadIdx.x;
    if (i < NNODES) g_deg[i] = 1;            // self-loop
}

__global__ void k_count(const int* __restrict__ ei) {
    int e = blockIdx.x * blockDim.x + threadIdx.x;
    if (e >= NEDGES) return;
    atomicAdd(&g_deg[ei[NEDGES + e]], 1);
}

__global__ void k_bsum() {                   // grid NBLK, block 256
    __shared__ int sm[256];
    int i = blockIdx.x * 256 + threadIdx.x;
    sm[threadIdx.x] = (i < NNODES) ? g_deg[i] : 0;
    __syncthreads();
    for (int o = 128; o; o >>= 1) {
        if (threadIdx.x < o) sm[threadIdx.x] += sm[threadIdx.x + o];
        __syncthreads();
    }
    if (threadIdx.x == 0) g_bsum[blockIdx.x] = sm[0];
}

__global__ void k_bscan() {                  // 1 block, 256 threads
    __shared__ int sm[512];
    int t = threadIdx.x;
    sm[t] = 0;
    sm[256 + t] = (t < NBLK) ? g_bsum[t] : 0;
    __syncthreads();
    for (int d = 1; d < 256; d <<= 1) {
        int v = sm[256 + t - d];
        __syncthreads();
        sm[256 + t] += v;
        __syncthreads();
    }
    g_boff[t] = sm[255 + t];                 // exclusive prefix
    if (t == 0) g_off[NNODES] = ETOT;
}

__global__ void k_offsets() {                // grid NBLK, block 256
    __shared__ int sm[512];
    int t = threadIdx.x;
    int i = blockIdx.x * 256 + t;
    int d = (i < NNODES) ? g_deg[i] : 0;
    sm[t] = 0;
    sm[256 + t] = d;
    __syncthreads();
    for (int dd = 1; dd < 256; dd <<= 1) {
        int v = sm[256 + t - dd];
        __syncthreads();
        sm[256 + t] += v;
        __syncthreads();
    }
    if (i < NNODES) {
        int run = g_boff[blockIdx.x] + sm[255 + t];
        g_off[i] = run;
        g_csr[run] = i;                      // self-loop at first slot
        g_cur[i] = run + 1;
    }
}

__global__ void k_scatter(const int* __restrict__ ei) {
    int e = blockIdx.x * blockDim.x + threadIdx.x;
    if (e >= NEDGES) return;
    int s = ei[e];
    int p = atomicAdd(&g_cur[ei[NEDGES + e]], 1);
    g_csr[p] = s;
}

// ---------------- embedding GEMM: h0 = x @ W_emb + b -------------------------
// 64 threads: thread owns out col k, W column in 128 regs, 32-node tile.
__global__ void __launch_bounds__(64) k_emb(const float* __restrict__ x,
                                            const float* __restrict__ W,
                                            const float* __restrict__ b) {
    __shared__ float xs[INF * 36];           // f-major, 36-float rows (16B aligned, conflict-padded)
    int k = threadIdx.x;
    int n0 = blockIdx.x * NT;
    float wc[INF];
    #pragma unroll
    for (int f = 0; f < INF; f++) wc[f] = W[f * HID + k];
    #pragma unroll
    for (int j = 0; j < 16; j++) {
        int idx = k + 64 * j;                // 0..1023 float4 slots
        int nl = idx >> 5;                   // node 0..31
        int fq = idx & 31;                   // quad 0..31
        int n = n0 + nl;
        float4 v = (n < NNODES) ? *(const float4*)&x[(size_t)n * INF + fq * 4]
                                : make_float4(0.f, 0.f, 0.f, 0.f);
        xs[(fq * 4 + 0) * 36 + nl] = v.x;
        xs[(fq * 4 + 1) * 36 + nl] = v.y;
        xs[(fq * 4 + 2) * 36 + nl] = v.z;
        xs[(fq * 4 + 3) * 36 + nl] = v.w;
    }
    __syncthreads();
    float acc[NT];
    #pragma unroll
    for (int j = 0; j < NT; j++) acc[j] = 0.f;
    #pragma unroll 4
    for (int f = 0; f < INF; f++) {
        const float4* row = (const float4*)&xs[f * 36];
        float w = wc[f];
        #pragma unroll
        for (int q = 0; q < 8; q++) {
            float4 hv = row[q];
            acc[q * 4 + 0] = fmaf(hv.x, w, acc[q * 4 + 0]);
            acc[q * 4 + 1] = fmaf(hv.y, w, acc[q * 4 + 1]);
            acc[q * 4 + 2] = fmaf(hv.z, w, acc[q * 4 + 2]);
            acc[q * 4 + 3] = fmaf(hv.w, w, acc[q * 4 + 3]);
        }
    }
    float bk = b[k];
    #pragma unroll
    for (int j = 0; j < NT; j++)
        g_h[(size_t)(n0 + j) * HID + k] = acc[j] + bk;
}

// ---------------- z GEMM: z = h @ W_gat  (50000x64 @ 64x256) ------------------
__global__ void __launch_bounds__(256) k_z(const float* __restrict__ Wg, int cur) {
    __shared__ float hs[HID * 36];
    int k = threadIdx.x;
    int n0 = blockIdx.x * NT;
    const float* h = g_h + (size_t)cur * NPAD * HID;
    float wc[HID];
    #pragma unroll
    for (int f = 0; f < HID; f++) wc[f] = Wg[f * ZW + k];
    #pragma unroll
    for (int j = 0; j < 2; j++) {
        int idx = k + 256 * j;               // 0..511 float4 slots
        int nl = idx >> 4;                   // node 0..31
        int fq = idx & 15;                   // quad 0..15
        float4 v = *(const float4*)&h[(size_t)(n0 + nl) * HID + fq * 4];
        hs[(fq * 4 + 0) * 36 + nl] = v.x;
        hs[(fq * 4 + 1) * 36 + nl] = v.y;
        hs[(fq * 4 + 2) * 36 + nl] = v.z;
        hs[(fq * 4 + 3) * 36 + nl] = v.w;
    }
    __syncthreads();
    float acc[NT];
    #pragma unroll
    for (int j = 0; j < NT; j++) acc[j] = 0.f;
    #pragma unroll 8
    for (int f = 0; f < HID; f++) {
        const float4* row = (const float4*)&hs[f * 36];
        float w = wc[f];
        #pragma unroll
        for (int q = 0; q < 8; q++) {
            float4 hv = row[q];
            acc[q * 4 + 0] = fmaf(hv.x, w, acc[q * 4 + 0]);
            acc[q * 4 + 1] = fmaf(hv.y, w, acc[q * 4 + 1]);
            acc[q * 4 + 2] = fmaf(hv.z, w, acc[q * 4 + 2]);
            acc[q * 4 + 3] = fmaf(hv.w, w, acc[q * 4 + 3]);
        }
    }
    float* z = (float*)g_z;
    #pragma unroll
    for (int j = 0; j < NT; j++)
        z[(size_t)(n0 + j) * ZW + k] = acc[j];
}

// ---------------- attention logits: warp per node -----------------------------
__global__ void k_att(const float* __restrict__ asrc,
                      const float* __restrict__ adst) {
    __shared__ float4 as4[64], ad4[64];
    int t = threadIdx.x;                     // 256
    if (t < 64) {
        as4[t] = ((const float4*)asrc)[t];
        ad4[t] = ((const float4*)adst)[t];
    }
    __syncthreads();
    int n = blockIdx.x * 8 + (t >> 5);       // grid 6250 -> exactly 50000
    int lane = t & 31;
    const float4* zr = g_z + (size_t)n * (ZW / 4);
    float4 z0 = zr[lane * 2], z1 = zr[lane * 2 + 1];
    float4 a0 = as4[lane * 2], a1 = as4[lane * 2 + 1];
    float4 d0 = ad4[lane * 2], d1 = ad4[lane * 2 + 1];
    float ps = z0.x*a0.x + z0.y*a0.y + z0.z*a0.z + z0.w*a0.w
             + z1.x*a1.x + z1.y*a1.y + z1.z*a1.z + z1.w*a1.w;
    float pd = z0.x*d0.x + z0.y*d0.y + z0.z*d0.z + z0.w*d0.w
             + z1.x*d1.x + z1.y*d1.y + z1.z*d1.z + z1.w*d1.w;
    #pragma unroll
    for (int o = 1; o <= 4; o <<= 1) {
        ps += __shfl_xor_sync(0xffffffffu, ps, o);
        pd += __shfl_xor_sync(0xffffffffu, pd, o);
    }
    if ((lane & 7) == 0) {
        int hh = lane >> 3;
        g_als[n * HEADS + hh] = ps;
        g_ald[n * HEADS + hh] = pd;
    }
}

// ---------------- per-dst aggregation (one warp per node, 2-way unroll) ------
__global__ void k_agg(const float* __restrict__ bg, int cur) {
    int wid = (blockIdx.x * blockDim.x + threadIdx.x) >> 5;
    if (wid >= NNODES) return;
    int n = wid;
    int lane = threadIdx.x & 31;
    int hh = lane >> 3;
    int fg = lane & 7;

    float ald = g_ald[n * HEADS + hh];
    float a0=0,a1=0,a2=0,a3=0,a4=0,a5=0,a6=0,a7=0;
    float dsum = 0.f;

    int beg = g_off[n], end = g_off[n + 1];
    int zoff = hh * 16 + fg * 2;
    for (int i = beg; i < end; i += 2) {
        int s0 = g_csr[i];
        bool h1 = (i + 1 < end);
        int s1 = h1 ? g_csr[i + 1] : s0;
        float e0 = g_als[s0 * HEADS + hh] + ald;
        float e1 = g_als[s1 * HEADS + hh] + ald;
        e0 = (e0 > 0.f) ? e0 : 0.2f * e0;
        e1 = (e1 > 0.f) ? e1 : 0.2f * e1;
        float w0 = __expf(e0);
        float w1 = h1 ? __expf(e1) : 0.f;
        float4 va0 = g_z[s0 * (ZW/4) + zoff];
        float4 vb0 = g_z[s0 * (ZW/4) + zoff + 1];
        float4 va1 = g_z[s1 * (ZW/4) + zoff];
        float4 vb1 = g_z[s1 * (ZW/4) + zoff + 1];
        dsum += w0 + w1;
        a0 = fmaf(w0, va0.x, a0); a1 = fmaf(w0, va0.y, a1);
        a2 = fmaf(w0, va0.z, a2); a3 = fmaf(w0, va0.w, a3);
        a4 = fmaf(w0, vb0.x, a4); a5 = fmaf(w0, vb0.y, a5);
        a6 = fmaf(w0, vb0.z, a6); a7 = fmaf(w0, vb0.w, a7);
        a0 = fmaf(w1, va1.x, a0); a1 = fmaf(w1, va1.y, a1);
        a2 = fmaf(w1, va1.z, a2); a3 = fmaf(w1, va1.w, a3);
        a4 = fmaf(w1, vb1.x, a4); a5 = fmaf(w1, vb1.y, a5);
        a6 = fmaf(w1, vb1.z, a6); a7 = fmaf(w1, vb1.w, a7);
    }
    float inv = 1.f / (dsum + 1e-16f);
    a0*=inv; a1*=inv; a2*=inv; a3*=inv; a4*=inv; a5*=inv; a6*=inv; a7*=inv;

    #pragma unroll
    for (int m = 8; m <= 16; m <<= 1) {
        a0 += __shfl_xor_sync(0xffffffffu, a0, m);
        a1 += __shfl_xor_sync(0xffffffffu, a1, m);
        a2 += __shfl_xor_sync(0xffffffffu, a2, m);
        a3 += __shfl_xor_sync(0xffffffffu, a3, m);
        a4 += __shfl_xor_sync(0xffffffffu, a4, m);
        a5 += __shfl_xor_sync(0xffffffffu, a5, m);
        a6 += __shfl_xor_sync(0xffffffffu, a6, m);
        a7 += __shfl_xor_sync(0xffffffffu, a7, m);
    }
    if (hh == 0) {
        int fb = fg * 8;
        float* o = g_h + (size_t)(cur ^ 1) * NPAD * HID + (size_t)n * HID + fb;
        o[0] = fmaxf(0.25f * a0 + bg[fb + 0], 0.f);
        o[1] = fmaxf(0.25f * a1 + bg[fb + 1], 0.f);
        o[2] = fmaxf(0.25f * a2 + bg[fb + 2], 0.f);
        o[3] = fmaxf(0.25f * a3 + bg[fb + 3], 0.f);
        o[4] = fmaxf(0.25f * a4 + bg[fb + 4], 0.f);
        o[5] = fmaxf(0.25f * a5 + bg[fb + 5], 0.f);
        o[6] = fmaxf(0.25f * a6 + bg[fb + 6], 0.f);
        o[7] = fmaxf(0.25f * a7 + bg[fb + 7], 0.f);
    }
}

// ---------------- global mean pool (batch sorted int32) ----------------------
__global__ void k_pool(const int* __restrict__ batch, int cur) {
    __shared__ int s_lo, s_hi;
    __shared__ float red[256];
    int g = blockIdx.x;
    if (threadIdx.x == 0) {
        int lo = 0, hi = NNODES;
        while (lo < hi) { int m = (lo + hi) >> 1; if (batch[m] < g) lo = m + 1; else hi = m; }
        s_lo = lo;
        lo = 0; hi = NNODES;
        while (lo < hi) { int m = (lo + hi) >> 1; if (batch[m] < g + 1) lo = m + 1; else hi = m; }
        s_hi = lo;
    }
    __syncthreads();
    int lo = s_lo, hi = s_hi;
    int f = threadIdx.x & 63, r = threadIdx.x >> 6;
    const float* h = g_h + (size_t)cur * NPAD * HID;
    float acc = 0.f;
    for (int n = lo + r; n < hi; n += 4) acc += h[(size_t)n * HID + f];
    red[threadIdx.x] = acc;
    __syncthreads();
    if (threadIdx.x < 64) {
        float v = red[f] + red[64 + f] + red[128 + f] + red[192 + f];
        float cnt = (float)max(hi - lo, 1);
        g_hg[g * HID + f] = v / cnt;
    }
}

// ---------------- final FC ----------------------------------------------------
__global__ void k_fc(const float* __restrict__ Wfc,
                     const float* __restrict__ bfc,
                     float* __restrict__ out) {
    __shared__ float hg[NG * HID];
    int t = threadIdx.x;
    for (int i = t; i < NG * HID; i += 256) hg[i] = g_hg[i];
    __syncthreads();
    int o = blockIdx.x * 256 + t;
    if (o >= OUTF) return;
    float bo = bfc[o];
    float acc[NG];
    #pragma unroll
    for (int g = 0; g < NG; g++) acc[g] = bo;
    for (int f = 0; f < HID; f++) {
        float w = Wfc[f * OUTF + o];
        #pragma unroll
        for (int g = 0; g < NG; g++) acc[g] = fmaf(hg[g * HID + f], w, acc[g]);
    }
    #pragma unroll
    for (int g = 0; g < NG; g++) out[(long long)g * OUTF + o] = acc[g];
}

// ---------------- launch --------------------------------------------------------
extern "C" void kernel_launch(void* const* d_in, const int* in_sizes, int n_in,
                              void* d_out, int out_size) {
    const float* x     = (const float*)d_in[0];
    const int*   ei    = (const int*)d_in[1];
    const int*   batch = (const int*)d_in[3];
    const float* W_emb = (const float*)d_in[4];
    const float* b_emb = (const float*)d_in[5];
    const float* W_gat = (const float*)d_in[6];
    const float* a_src = (const float*)d_in[7];
    const float* a_dst = (const float*)d_in[8];
    const float* b_gat = (const float*)d_in[9];
    const float* W_fc  = (const float*)d_in[10];
    const float* b_fc  = (const float*)d_in[11];
    float* out = (float*)d_out;

    k_init_deg<<<NBLK, 256>>>();
    k_count<<<(NEDGES + 255) / 256, 256>>>(ei);
    k_bsum<<<NBLK, 256>>>();
    k_bscan<<<1, 256>>>();
    k_offsets<<<NBLK, 256>>>();
    k_scatter<<<(NEDGES + 255) / 256, 256>>>(ei);
    k_emb<<<NTILES, 64>>>(x, W_emb, b_emb);

    int cur = 0;
    for (int l = 0; l < 3; l++) {
        k_z<<<NTILES, 256>>>(W_gat + (size_t)l * HID * ZW, cur);
        k_att<<<NNODES / 8, 256>>>(a_src + (size_t)l * HEADS * HID,
                                   a_dst + (size_t)l * HEADS * HID);
        k_agg<<<(NNODES * 32 + 255) / 256, 256>>>(b_gat + (size_t)l * HID, cur);
        cur ^= 1;
    }

    k_pool<<<NG, 256>>>(batch, cur);
    k_fc<<<(OUTF + 255) / 256, 256>>>(W_fc, b_fc, out);
}

// round 6
// speedup vs baseline: 1.5997x; 1.0074x over previous
#include <cuda_runtime.h>
#include <cuda_bf16.h>
#include <math.h>

#define NNODES 50000
#define NEDGES 500000
#define ETOT   (NEDGES + NNODES)
#define INF    128
#define HID    64
#define HEADS  4
#define ZW     (HEADS * HID)       // 256
#define NG     16
#define OUTF   326000
#define NT     32                  // node tile
#define NPAD   50016               // ceil(NNODES/NT)*NT
#define NTILES (NPAD / NT)         // 1563
#define NBLK   196                 // ceil(NNODES/256)

// ---------------- scratch ----------------------------------------------------
__device__ float  g_h[2 * NPAD * HID];      // ping-pong node features
__device__ float4 g_z[NPAD * (ZW / 4)];     // projected features
__device__ float  g_als[NNODES * HEADS];
__device__ float  g_ald[NNODES * HEADS];
__device__ int    g_deg[NNODES];
__device__ int    g_off[NNODES + 1];
__device__ int    g_cur[NNODES];
__device__ int    g_csr[ETOT];
__device__ int    g_bsum[256];
__device__ int    g_boff[256];
__device__ float  g_hg[NG * HID];

// ---------------- CSR build --------------------------------------------------
__global__ void k_init_deg() {
    int i = blockIdx.x * blockDim.x + threadIdx.x;
    if (i < NNODES) g_deg[i] = 1;            // self-loop
}

__global__ void k_count(const int* __restrict__ ei) {
    int e = blockIdx.x * blockDim.x + threadIdx.x;
    if (e >= NEDGES) return;
    atomicAdd(&g_deg[ei[NEDGES + e]], 1);
}

__global__ void k_bsum() {                   // grid NBLK, block 256
    __shared__ int sm[256];
    int i = blockIdx.x * 256 + threadIdx.x;
    sm[threadIdx.x] = (i < NNODES) ? g_deg[i] : 0;
    __syncthreads();
    for (int o = 128; o; o >>= 1) {
        if (threadIdx.x < o) sm[threadIdx.x] += sm[threadIdx.x + o];
        __syncthreads();
    }
    if (threadIdx.x == 0) g_bsum[blockIdx.x] = sm[0];
}

__global__ void k_bscan() {                  // 1 block, 256 threads
    __shared__ int sm[512];
    int t = threadIdx.x;
    sm[t] = 0;
    sm[256 + t] = (t < NBLK) ? g_bsum[t] : 0;
    __syncthreads();
    for (int d = 1; d < 256; d <<= 1) {
        int v = sm[256 + t - d];
        __syncthreads();
        sm[256 + t] += v;
        __syncthreads();
    }
    g_boff[t] = sm[255 + t];                 // exclusive prefix
    if (t == 0) g_off[NNODES] = ETOT;
}

__global__ void k_offsets() {                // grid NBLK, block 256
    __shared__ int sm[512];
    int t = threadIdx.x;
    int i = blockIdx.x * 256 + t;
    int d = (i < NNODES) ? g_deg[i] : 0;
    sm[t] = 0;
    sm[256 + t] = d;
    __syncthreads();
    for (int dd = 1; dd < 256; dd <<= 1) {
        int v = sm[256 + t - dd];
        __syncthreads();
        sm[256 + t] += v;
        __syncthreads();
    }
    if (i < NNODES) {
        int run = g_boff[blockIdx.x] + sm[255 + t];
        g_off[i] = run;
        g_csr[run] = i;                      // self-loop at first slot
        g_cur[i] = run + 1;
    }
}

__global__ void k_scatter(const int* __restrict__ ei) {
    int e = blockIdx.x * blockDim.x + threadIdx.x;
    if (e >= NEDGES) return;
    int s = ei[e];
    int p = atomicAdd(&g_cur[ei[NEDGES + e]], 1);
    g_csr[p] = s;
}

// ---------------- embedding GEMM: h0 = x @ W_emb + b -------------------------
__global__ void __launch_bounds__(64) k_emb(const float* __restrict__ x,
                                            const float* __restrict__ W,
                                            const float* __restrict__ b) {
    __shared__ float xs[INF * 36];
    int k = threadIdx.x;
    int n0 = blockIdx.x * NT;
    float wc[INF];
    #pragma unroll
    for (int f = 0; f < INF; f++) wc[f] = W[f * HID + k];
    #pragma unroll
    for (int j = 0; j < 16; j++) {
        int idx = k + 64 * j;
        int nl = idx >> 5;
        int fq = idx & 31;
        int n = n0 + nl;
        float4 v = (n < NNODES) ? *(const float4*)&x[(size_t)n * INF + fq * 4]
                                : make_float4(0.f, 0.f, 0.f, 0.f);
        xs[(fq * 4 + 0) * 36 + nl] = v.x;
        xs[(fq * 4 + 1) * 36 + nl] = v.y;
        xs[(fq * 4 + 2) * 36 + nl] = v.z;
        xs[(fq * 4 + 3) * 36 + nl] = v.w;
    }
    __syncthreads();
    float acc[NT];
    #pragma unroll
    for (int j = 0; j < NT; j++) acc[j] = 0.f;
    #pragma unroll 4
    for (int f = 0; f < INF; f++) {
        const float4* row = (const float4*)&xs[f * 36];
        float w = wc[f];
        #pragma unroll
        for (int q = 0; q < 8; q++) {
            float4 hv = row[q];
            acc[q * 4 + 0] = fmaf(hv.x, w, acc[q * 4 + 0]);
            acc[q * 4 + 1] = fmaf(hv.y, w, acc[q * 4 + 1]);
            acc[q * 4 + 2] = fmaf(hv.z, w, acc[q * 4 + 2]);
            acc[q * 4 + 3] = fmaf(hv.w, w, acc[q * 4 + 3]);
        }
    }
    float bk = b[k];
    #pragma unroll
    for (int j = 0; j < NT; j++)
        g_h[(size_t)(n0 + j) * HID + k] = acc[j] + bk;
}

// ---------------- z GEMM: z = h @ W_gat  (50000x64 @ 64x256) ------------------
__global__ void __launch_bounds__(256) k_z(const float* __restrict__ Wg, int cur) {
    __shared__ float hs[HID * 36];
    int k = threadIdx.x;
    int n0 = blockIdx.x * NT;
    const float* h = g_h + (size_t)cur * NPAD * HID;
    float wc[HID];
    #pragma unroll
    for (int f = 0; f < HID; f++) wc[f] = Wg[f * ZW + k];
    #pragma unroll
    for (int j = 0; j < 2; j++) {
        int idx = k + 256 * j;
        int nl = idx >> 4;
        int fq = idx & 15;
        float4 v = *(const float4*)&h[(size_t)(n0 + nl) * HID + fq * 4];
        hs[(fq * 4 + 0) * 36 + nl] = v.x;
        hs[(fq * 4 + 1) * 36 + nl] = v.y;
        hs[(fq * 4 + 2) * 36 + nl] = v.z;
        hs[(fq * 4 + 3) * 36 + nl] = v.w;
    }
    __syncthreads();
    float acc[NT];
    #pragma unroll
    for (int j = 0; j < NT; j++) acc[j] = 0.f;
    #pragma unroll 8
    for (int f = 0; f < HID; f++) {
        const float4* row = (const float4*)&hs[f * 36];
        float w = wc[f];
        #pragma unroll
        for (int q = 0; q < 8; q++) {
            float4 hv = row[q];
            acc[q * 4 + 0] = fmaf(hv.x, w, acc[q * 4 + 0]);
            acc[q * 4 + 1] = fmaf(hv.y, w, acc[q * 4 + 1]);
            acc[q * 4 + 2] = fmaf(hv.z, w, acc[q * 4 + 2]);
            acc[q * 4 + 3] = fmaf(hv.w, w, acc[q * 4 + 3]);
        }
    }
    float* z = (float*)g_z;
    #pragma unroll
    for (int j = 0; j < NT; j++)
        z[(size_t)(n0 + j) * ZW + k] = acc[j];
}

// ---------------- attention logits: warp per node -----------------------------
__global__ void __launch_bounds__(256) k_att(const float* __restrict__ asrc,
                                             const float* __restrict__ adst) {
    __shared__ float4 as4[64], ad4[64];
    int t = threadIdx.x;
    if (t < 64) {
        as4[t] = ((const float4*)asrc)[t];
        ad4[t] = ((const float4*)adst)[t];
    }
    __syncthreads();
    int n = blockIdx.x * 8 + (t >> 5);
    int lane = t & 31;
    const float4* zr = g_z + (size_t)n * (ZW / 4);
    float4 z0 = zr[lane * 2], z1 = zr[lane * 2 + 1];
    float4 a0 = as4[lane * 2], a1 = as4[lane * 2 + 1];
    float4 d0 = ad4[lane * 2], d1 = ad4[lane * 2 + 1];
    float ps = z0.x*a0.x + z0.y*a0.y + z0.z*a0.z + z0.w*a0.w
             + z1.x*a1.x + z1.y*a1.y + z1.z*a1.z + z1.w*a1.w;
    float pd = z0.x*d0.x + z0.y*d0.y + z0.z*d0.z + z0.w*d0.w
             + z1.x*d1.x + z1.y*d1.y + z1.z*d1.z + z1.w*d1.w;
    #pragma unroll
    for (int o = 1; o <= 4; o <<= 1) {
        ps += __shfl_xor_sync(0xffffffffu, ps, o);
        pd += __shfl_xor_sync(0xffffffffu, pd, o);
    }
    if ((lane & 7) == 0) {
        int hh = lane >> 3;
        g_als[n * HEADS + hh] = ps;
        g_ald[n * HEADS + hh] = pd;
    }
}

// ---------------- per-dst aggregation (one warp per node, 4-way unroll) ------
__global__ void __launch_bounds__(256) k_agg(const float* __restrict__ bg, int cur) {
    int wid = (blockIdx.x * blockDim.x + threadIdx.x) >> 5;
    if (wid >= NNODES) return;
    int n = wid;
    int lane = threadIdx.x & 31;
    int hh = lane >> 3;
    int fg = lane & 7;

    float ald = g_ald[n * HEADS + hh];
    float a0=0,a1=0,a2=0,a3=0,a4=0,a5=0,a6=0,a7=0;
    float dsum = 0.f;

    int beg = g_off[n], end = g_off[n + 1];
    int zoff = hh * 16 + fg * 2;
    int i = beg;
    // 4-wide bundles: batch all loads before FMAs (MLP >= 12)
    for (; i + 4 <= end; i += 4) {
        int s0 = g_csr[i], s1 = g_csr[i+1], s2 = g_csr[i+2], s3 = g_csr[i+3];
        float l0 = g_als[s0 * HEADS + hh];
        float l1 = g_als[s1 * HEADS + hh];
        float l2 = g_als[s2 * HEADS + hh];
        float l3 = g_als[s3 * HEADS + hh];
        float4 va0 = g_z[s0 * (ZW/4) + zoff], vb0 = g_z[s0 * (ZW/4) + zoff + 1];
        float4 va1 = g_z[s1 * (ZW/4) + zoff], vb1 = g_z[s1 * (ZW/4) + zoff + 1];
        float4 va2 = g_z[s2 * (ZW/4) + zoff], vb2 = g_z[s2 * (ZW/4) + zoff + 1];
        float4 va3 = g_z[s3 * (ZW/4) + zoff], vb3 = g_z[s3 * (ZW/4) + zoff + 1];
        float e0 = l0 + ald, e1 = l1 + ald, e2 = l2 + ald, e3 = l3 + ald;
        e0 = (e0 > 0.f) ? e0 : 0.2f * e0;
        e1 = (e1 > 0.f) ? e1 : 0.2f * e1;
        e2 = (e2 > 0.f) ? e2 : 0.2f * e2;
        e3 = (e3 > 0.f) ? e3 : 0.2f * e3;
        float w0 = __expf(e0), w1 = __expf(e1), w2 = __expf(e2), w3 = __expf(e3);
        dsum += (w0 + w1) + (w2 + w3);
        a0 = fmaf(w0, va0.x, a0); a1 = fmaf(w0, va0.y, a1);
        a2 = fmaf(w0, va0.z, a2); a3 = fmaf(w0, va0.w, a3);
        a4 = fmaf(w0, vb0.x, a4); a5 = fmaf(w0, vb0.y, a5);
        a6 = fmaf(w0, vb0.z, a6); a7 = fmaf(w0, vb0.w, a7);
        a0 = fmaf(w1, va1.x, a0); a1 = fmaf(w1, va1.y, a1);
        a2 = fmaf(w1, va1.z, a2); a3 = fmaf(w1, va1.w, a3);
        a4 = fmaf(w1, vb1.x, a4); a5 = fmaf(w1, vb1.y, a5);
        a6 = fmaf(w1, vb1.z, a6); a7 = fmaf(w1, vb1.w, a7);
        a0 = fmaf(w2, va2.x, a0); a1 = fmaf(w2, va2.y, a1);
        a2 = fmaf(w2, va2.z, a2); a3 = fmaf(w2, va2.w, a3);
        a4 = fmaf(w2, vb2.x, a4); a5 = fmaf(w2, vb2.y, a5);
        a6 = fmaf(w2, vb2.z, a6); a7 = fmaf(w2, vb2.w, a7);
        a0 = fmaf(w3, va3.x, a0); a1 = fmaf(w3, va3.y, a1);
        a2 = fmaf(w3, va3.z, a2); a3 = fmaf(w3, va3.w, a3);
        a4 = fmaf(w3, vb3.x, a4); a5 = fmaf(w3, vb3.y, a5);
        a6 = fmaf(w3, vb3.z, a6); a7 = fmaf(w3, vb3.w, a7);
    }
    for (; i < end; i++) {
        int s = g_csr[i];
        float e = g_als[s * HEADS + hh] + ald;
        e = (e > 0.f) ? e : 0.2f * e;
        float w = __expf(e);
        float4 va = g_z[s * (ZW/4) + zoff];
        float4 vb = g_z[s * (ZW/4) + zoff + 1];
        dsum += w;
        a0 = fmaf(w, va.x, a0); a1 = fmaf(w, va.y, a1);
        a2 = fmaf(w, va.z, a2); a3 = fmaf(w, va.w, a3);
        a4 = fmaf(w, vb.x, a4); a5 = fmaf(w, vb.y, a5);
        a6 = fmaf(w, vb.z, a6); a7 = fmaf(w, vb.w, a7);
    }
    float inv = 1.f / (dsum + 1e-16f);
    a0*=inv; a1*=inv; a2*=inv; a3*=inv; a4*=inv; a5*=inv; a6*=inv; a7*=inv;

    #pragma unroll
    for (int m = 8; m <= 16; m <<= 1) {
        a0 += __shfl_xor_sync(0xffffffffu, a0, m);
        a1 += __shfl_xor_sync(0xffffffffu, a1, m);
        a2 += __shfl_xor_sync(0xffffffffu, a2, m);
        a3 += __shfl_xor_sync(0xffffffffu, a3, m);
        a4 += __shfl_xor_sync(0xffffffffu, a4, m);
        a5 += __shfl_xor_sync(0xffffffffu, a5, m);
        a6 += __shfl_xor_sync(0xffffffffu, a6, m);
        a7 += __shfl_xor_sync(0xffffffffu, a7, m);
    }
    if (hh == 0) {
        int fb = fg * 8;
        float* o = g_h + (size_t)(cur ^ 1) * NPAD * HID + (size_t)n * HID + fb;
        o[0] = fmaxf(0.25f * a0 + bg[fb + 0], 0.f);
        o[1] = fmaxf(0.25f * a1 + bg[fb + 1], 0.f);
        o[2] = fmaxf(0.25f * a2 + bg[fb + 2], 0.f);
        o[3] = fmaxf(0.25f * a3 + bg[fb + 3], 0.f);
        o[4] = fmaxf(0.25f * a4 + bg[fb + 4], 0.f);
        o[5] = fmaxf(0.25f * a5 + bg[fb + 5], 0.f);
        o[6] = fmaxf(0.25f * a6 + bg[fb + 6], 0.f);
        o[7] = fmaxf(0.25f * a7 + bg[fb + 7], 0.f);
    }
}

// ---------------- global mean pool (batch sorted int32) ----------------------
__global__ void k_pool(const int* __restrict__ batch, int cur) {
    __shared__ int s_lo, s_hi;
    __shared__ float red[256];
    int g = blockIdx.x;
    if (threadIdx.x == 0) {
        int lo = 0, hi = NNODES;
        while (lo < hi) { int m = (lo + hi) >> 1; if (batch[m] < g) lo = m + 1; else hi = m; }
        s_lo = lo;
        lo = 0; hi = NNODES;
        while (lo < hi) { int m = (lo + hi) >> 1; if (batch[m] < g + 1) lo = m + 1; else hi = m; }
        s_hi = lo;
    }
    __syncthreads();
    int lo = s_lo, hi = s_hi;
    int f = threadIdx.x & 63, r = threadIdx.x >> 6;
    const float* h = g_h + (size_t)cur * NPAD * HID;
    float acc = 0.f;
    for (int n = lo + r; n < hi; n += 4) acc += h[(size_t)n * HID + f];
    red[threadIdx.x] = acc;
    __syncthreads();
    if (threadIdx.x < 64) {
        float v = red[f] + red[64 + f] + red[128 + f] + red[192 + f];
        float cnt = (float)max(hi - lo, 1);
        g_hg[g * HID + f] = v / cnt;
    }
}

// ---------------- final FC ----------------------------------------------------
__global__ void k_fc(const float* __restrict__ Wfc,
                     const float* __restrict__ bfc,
                     float* __restrict__ out) {
    __shared__ float hg[NG * HID];
    int t = threadIdx.x;
    for (int i = t; i < NG * HID; i += 256) hg[i] = g_hg[i];
    __syncthreads();
    int o = blockIdx.x * 256 + t;
    if (o >= OUTF) return;
    float bo = bfc[o];
    float acc[NG];
    #pragma unroll
    for (int g = 0; g < NG; g++) acc[g] = bo;
    for (int f = 0; f < HID; f++) {
        float w = Wfc[f * OUTF + o];
        #pragma unroll
        for (int g = 0; g < NG; g++) acc[g] = fmaf(hg[g * HID + f], w, acc[g]);
    }
    #pragma unroll
    for (int g = 0; g < NG; g++) out[(long long)g * OUTF + o] = acc[g];
}

// ---------------- launch --------------------------------------------------------
extern "C" void kernel_launch(void* const* d_in, const int* in_sizes, int n_in,
                              void* d_out, int out_size) {
    const float* x     = (const float*)d_in[0];
    const int*   ei    = (const int*)d_in[1];
    const int*   batch = (const int*)d_in[3];
    const float* W_emb = (const float*)d_in[4];
    const float* b_emb = (const float*)d_in[5];
    const float* W_gat = (const float*)d_in[6];
    const float* a_src = (const float*)d_in[7];
    const float* a_dst = (const float*)d_in[8];
    const float* b_gat = (const float*)d_in[9];
    const float* W_fc  = (const float*)d_in[10];
    const float* b_fc  = (const float*)d_in[11];
    float* out = (float*)d_out;

    // Order chosen so launch #4 (= ncu capture window) is k_z.
    k_init_deg<<<NBLK, 256>>>();
    k_count<<<(NEDGES + 255) / 256, 256>>>(ei);
    k_emb<<<NTILES, 64>>>(x, W_emb, b_emb);
    k_z<<<NTILES, 256>>>(W_gat, 0);                       // layer 0 z
    k_bsum<<<NBLK, 256>>>();
    k_bscan<<<1, 256>>>();
    k_offsets<<<NBLK, 256>>>();
    k_scatter<<<(NEDGES + 255) / 256, 256>>>(ei);
    k_att<<<NNODES / 8, 256>>>(a_src, a_dst);
    k_agg<<<(NNODES * 32 + 255) / 256, 256>>>(b_gat, 0);

    int cur = 1;
    for (int l = 1; l < 3; l++) {
        k_z<<<NTILES, 256>>>(W_gat + (size_t)l * HID * ZW, cur);
        k_att<<<NNODES / 8, 256>>>(a_src + (size_t)l * HEADS * HID,
                                   a_dst + (size_t)l * HEADS * HID);
        k_agg<<<(NNODES * 32 + 255) / 256, 256>>>(b_gat + (size_t)l * HID, cur);
        cur ^= 1;
    }

    k_pool<<<NG, 256>>>(batch, cur);
    k_fc<<<(OUTF + 255) / 256, 256>>>(W_fc, b_fc, out);
}

// round 7
// speedup vs baseline: 1.8533x; 1.1586x over previous
#include <cuda_runtime.h>
#include <cuda_bf16.h>
#include <math.h>

typedef unsigned long long ull;

#define NNODES 50000
#define NEDGES 500000
#define ETOT   (NEDGES + NNODES)
#define INF    128
#define HID    64
#define HEADS  4
#define ZW     (HEADS * HID)       // 256
#define NG     16
#define OUTF   326000
#define NT     32                  // emb node tile
#define NPAD   50048               // multiple of 64 (and 32)
#define NTILES (NPAD / NT)         // 1564
#define NZBLK  (NPAD / 64)         // 782
#define NBLK   196                 // ceil(NNODES/256)

#define FMA2(d,a,b,c) asm("fma.rn.f32x2 %0, %1, %2, %3;" : "=l"(d) : "l"(a), "l"(b), "l"(c))
#define PK2(d,lo,hi)  asm("mov.b64 %0, {%1, %2};" : "=l"(d) : "f"(lo), "f"(hi))
#define UPK2(lo,hi,s) asm("mov.b64 {%0, %1}, %2;" : "=f"(lo), "=f"(hi) : "l"(s))

// ---------------- scratch ----------------------------------------------------
__device__ float  g_h[2 * NPAD * HID];
__device__ float4 g_z[NPAD * (ZW / 4)];
__device__ float  g_als[NPAD * HEADS];
__device__ float  g_ald[NPAD * HEADS];
__device__ int    g_deg[NNODES];
__device__ int    g_off[NNODES + 1];
__device__ int    g_cur[NNODES];
__device__ int    g_csr[ETOT];
__device__ int    g_bsum[256];
__device__ int    g_boff[256];
__device__ float  g_hg[NG * HID];

// ---------------- CSR build --------------------------------------------------
__global__ void k_init_deg() {
    int i = blockIdx.x * blockDim.x + threadIdx.x;
    if (i < NNODES) g_deg[i] = 1;            // self-loop
}

__global__ void k_count(const int* __restrict__ ei) {
    int e = blockIdx.x * blockDim.x + threadIdx.x;
    if (e >= NEDGES) return;
    atomicAdd(&g_deg[ei[NEDGES + e]], 1);
}

__global__ void k_bsum() {
    __shared__ int sm[256];
    int i = blockIdx.x * 256 + threadIdx.x;
    sm[threadIdx.x] = (i < NNODES) ? g_deg[i] : 0;
    __syncthreads();
    for (int o = 128; o; o >>= 1) {
        if (threadIdx.x < o) sm[threadIdx.x] += sm[threadIdx.x + o];
        __syncthreads();
    }
    if (threadIdx.x == 0) g_bsum[blockIdx.x] = sm[0];
}

__global__ void k_bscan() {
    __shared__ int sm[512];
    int t = threadIdx.x;
    sm[t] = 0;
    sm[256 + t] = (t < NBLK) ? g_bsum[t] : 0;
    __syncthreads();
    for (int d = 1; d < 256; d <<= 1) {
        int v = sm[256 + t - d];
        __syncthreads();
        sm[256 + t] += v;
        __syncthreads();
    }
    g_boff[t] = sm[255 + t];
    if (t == 0) g_off[NNODES] = ETOT;
}

__global__ void k_offsets() {
    __shared__ int sm[512];
    int t = threadIdx.x;
    int i = blockIdx.x * 256 + t;
    int d = (i < NNODES) ? g_deg[i] : 0;
    sm[t] = 0;
    sm[256 + t] = d;
    __syncthreads();
    for (int dd = 1; dd < 256; dd <<= 1) {
        int v = sm[256 + t - dd];
        __syncthreads();
        sm[256 + t] += v;
        __syncthreads();
    }
    if (i < NNODES) {
        int run = g_boff[blockIdx.x] + sm[255 + t];
        g_off[i] = run;
        g_csr[run] = i;
        g_cur[i] = run + 1;
    }
}

__global__ void k_scatter(const int* __restrict__ ei) {
    int e = blockIdx.x * blockDim.x + threadIdx.x;
    if (e >= NEDGES) return;
    int s = ei[e];
    int p = atomicAdd(&g_cur[ei[NEDGES + e]], 1);
    g_csr[p] = s;
}

// ---------------- embedding GEMM ----------------------------------------------
__global__ void __launch_bounds__(64) k_emb(const float* __restrict__ x,
                                            const float* __restrict__ W,
                                            const float* __restrict__ b) {
    __shared__ float xs[INF * 36];
    int k = threadIdx.x;
    int n0 = blockIdx.x * NT;
    float wc[INF];
    #pragma unroll
    for (int f = 0; f < INF; f++) wc[f] = W[f * HID + k];
    #pragma unroll
    for (int j = 0; j < 16; j++) {
        int idx = k + 64 * j;
        int nl = idx >> 5;
        int fq = idx & 31;
        int n = n0 + nl;
        float4 v = (n < NNODES) ? *(const float4*)&x[(size_t)n * INF + fq * 4]
                                : make_float4(0.f, 0.f, 0.f, 0.f);
        xs[(fq * 4 + 0) * 36 + nl] = v.x;
        xs[(fq * 4 + 1) * 36 + nl] = v.y;
        xs[(fq * 4 + 2) * 36 + nl] = v.z;
        xs[(fq * 4 + 3) * 36 + nl] = v.w;
    }
    __syncthreads();
    float acc[NT];
    #pragma unroll
    for (int j = 0; j < NT; j++) acc[j] = 0.f;
    #pragma unroll 4
    for (int f = 0; f < INF; f++) {
        const float4* row = (const float4*)&xs[f * 36];
        float w = wc[f];
        #pragma unroll
        for (int q = 0; q < 8; q++) {
            float4 hv = row[q];
            acc[q * 4 + 0] = fmaf(hv.x, w, acc[q * 4 + 0]);
            acc[q * 4 + 1] = fmaf(hv.y, w, acc[q * 4 + 1]);
            acc[q * 4 + 2] = fmaf(hv.z, w, acc[q * 4 + 2]);
            acc[q * 4 + 3] = fmaf(hv.w, w, acc[q * 4 + 3]);
        }
    }
    float bk = b[k];
    #pragma unroll
    for (int j = 0; j < NT; j++)
        g_h[(size_t)(n0 + j) * HID + k] = acc[j] + bk;
}

// ---------------- z GEMM (8x8 reg tile, f32x2) + fused attention logits -------
// block: 64 nodes x 256 cols; warp ni: nodes [ni*8, ni*8+8); lane cj: cols [cj*8, cj*8+8)
__global__ void __launch_bounds__(256, 2) k_z(const float* __restrict__ Wg,
                                              const float* __restrict__ asrc,
                                              const float* __restrict__ adst,
                                              int cur) {
    __shared__ float4 ws4[32 * 64];          // W chunk [32f][256c]  32KB
    __shared__ __align__(16) float hs[32 * 68];  // h chunk [32f][64n pad] 8.7KB
    int tid = threadIdx.x;
    int n0 = blockIdx.x * 64;
    int ni = tid >> 5;
    int cj = tid & 31;
    const float* h = g_h + (size_t)cur * NPAD * HID;

    ull acc[8][4];                            // [col c][node-pair p]
    #pragma unroll
    for (int c = 0; c < 8; c++)
        #pragma unroll
        for (int p = 0; p < 4; p++) acc[c][p] = 0ull;

    #pragma unroll
    for (int ch = 0; ch < 2; ch++) {
        int fb = ch * 32;
        __syncthreads();
        const float4* Wg4 = (const float4*)(Wg + fb * ZW);
        #pragma unroll
        for (int j = 0; j < 8; j++) ws4[tid + 256 * j] = Wg4[tid + 256 * j];
        #pragma unroll
        for (int j = 0; j < 2; j++) {
            int idx = tid + 256 * j;
            int nl = idx & 63;
            int fq = idx >> 6;
            float4 v = *(const float4*)&h[(size_t)(n0 + nl) * HID + fb + fq * 4];
            hs[(fq * 4 + 0) * 68 + nl] = v.x;
            hs[(fq * 4 + 1) * 68 + nl] = v.y;
            hs[(fq * 4 + 2) * 68 + nl] = v.z;
            hs[(fq * 4 + 3) * 68 + nl] = v.w;
        }
        __syncthreads();
        #pragma unroll 2
        for (int f = 0; f < 32; f++) {
            float4 ha = *(const float4*)&hs[f * 68 + ni * 8];
            float4 hb = *(const float4*)&hs[f * 68 + ni * 8 + 4];
            float4 wa = ws4[f * 64 + cj * 2];
            float4 wb = ws4[f * 64 + cj * 2 + 1];
            ull hp[4];
            PK2(hp[0], ha.x, ha.y); PK2(hp[1], ha.z, ha.w);
            PK2(hp[2], hb.x, hb.y); PK2(hp[3], hb.z, hb.w);
            float wv[8] = {wa.x, wa.y, wa.z, wa.w, wb.x, wb.y, wb.z, wb.w};
            #pragma unroll
            for (int c = 0; c < 8; c++) {
                ull wd; PK2(wd, wv[c], wv[c]);
                #pragma unroll
                for (int p = 0; p < 4; p++) FMA2(acc[c][p], hp[p], wd, acc[c][p]);
            }
        }
    }

    // ---- fused attention logits: per-head dot over this thread's 8 cols ----
    float4 sa0 = *(const float4*)&asrc[cj * 8];
    float4 sa1 = *(const float4*)&asrc[cj * 8 + 4];
    float4 sd0 = *(const float4*)&adst[cj * 8];
    float4 sd1 = *(const float4*)&adst[cj * 8 + 4];
    float sav[8] = {sa0.x, sa0.y, sa0.z, sa0.w, sa1.x, sa1.y, sa1.z, sa1.w};
    float sdv[8] = {sd0.x, sd0.y, sd0.z, sd0.w, sd1.x, sd1.y, sd1.z, sd1.w};
    ull ds[4] = {0, 0, 0, 0}, dd[4] = {0, 0, 0, 0};
    #pragma unroll
    for (int c = 0; c < 8; c++) {
        ull t;
        PK2(t, sav[c], sav[c]);
        #pragma unroll
        for (int p = 0; p < 4; p++) FMA2(ds[p], acc[c][p], t, ds[p]);
        PK2(t, sdv[c], sdv[c]);
        #pragma unroll
        for (int p = 0; p < 4; p++) FMA2(dd[p], acc[c][p], t, dd[p]);
    }
    float dsl[8], ddl[8];
    #pragma unroll
    for (int p = 0; p < 4; p++) {
        UPK2(dsl[2 * p], dsl[2 * p + 1], ds[p]);
        UPK2(ddl[2 * p], ddl[2 * p + 1], dd[p]);
    }
    #pragma unroll
    for (int m = 0; m < 8; m++) {
        #pragma unroll
        for (int o = 1; o <= 4; o <<= 1) {
            dsl[m] += __shfl_xor_sync(0xffffffffu, dsl[m], o);
            ddl[m] += __shfl_xor_sync(0xffffffffu, ddl[m], o);
        }
    }
    if ((cj & 7) == 0) {
        int hh = cj >> 3;
        #pragma unroll
        for (int m = 0; m < 8; m++) {
            int n = n0 + ni * 8 + m;
            g_als[n * HEADS + hh] = dsl[m];
            g_ald[n * HEADS + hh] = ddl[m];
        }
    }

    // ---- store z tile ----
    float* zf = (float*)g_z;
    #pragma unroll
    for (int p = 0; p < 4; p++) {
        float lo[8], hi[8];
        #pragma unroll
        for (int c = 0; c < 8; c++) UPK2(lo[c], hi[c], acc[c][p]);
        float* za = zf + (size_t)(n0 + ni * 8 + 2 * p) * ZW + cj * 8;
        float* zb = za + ZW;
        ((float4*)za)[0] = make_float4(lo[0], lo[1], lo[2], lo[3]);
        ((float4*)za)[1] = make_float4(lo[4], lo[5], lo[6], lo[7]);
        ((float4*)zb)[0] = make_float4(hi[0], hi[1], hi[2], hi[3]);
        ((float4*)zb)[1] = make_float4(hi[4], hi[5], hi[6], hi[7]);
    }
}

// ---------------- per-dst aggregation (one warp per node, 4-way unroll) ------
__global__ void __launch_bounds__(256) k_agg(const float* __restrict__ bg, int cur) {
    int wid = (blockIdx.x * blockDim.x + threadIdx.x) >> 5;
    if (wid >= NNODES) return;
    int n = wid;
    int lane = threadIdx.x & 31;
    int hh = lane >> 3;
    int fg = lane & 7;

    float ald = g_ald[n * HEADS + hh];
    float a0=0,a1=0,a2=0,a3=0,a4=0,a5=0,a6=0,a7=0;
    float dsum = 0.f;

    int beg = g_off[n], end = g_off[n + 1];
    int zoff = hh * 16 + fg * 2;
    int i = beg;
    for (; i + 4 <= end; i += 4) {
        int s0 = g_csr[i], s1 = g_csr[i+1], s2 = g_csr[i+2], s3 = g_csr[i+3];
        float l0 = g_als[s0 * HEADS + hh];
        float l1 = g_als[s1 * HEADS + hh];
        float l2 = g_als[s2 * HEADS + hh];
        float l3 = g_als[s3 * HEADS + hh];
        float4 va0 = g_z[s0 * (ZW/4) + zoff], vb0 = g_z[s0 * (ZW/4) + zoff + 1];
        float4 va1 = g_z[s1 * (ZW/4) + zoff], vb1 = g_z[s1 * (ZW/4) + zoff + 1];
        float4 va2 = g_z[s2 * (ZW/4) + zoff], vb2 = g_z[s2 * (ZW/4) + zoff + 1];
        float4 va3 = g_z[s3 * (ZW/4) + zoff], vb3 = g_z[s3 * (ZW/4) + zoff + 1];
        float e0 = l0 + ald, e1 = l1 + ald, e2 = l2 + ald, e3 = l3 + ald;
        e0 = (e0 > 0.f) ? e0 : 0.2f * e0;
        e1 = (e1 > 0.f) ? e1 : 0.2f * e1;
        e2 = (e2 > 0.f) ? e2 : 0.2f * e2;
        e3 = (e3 > 0.f) ? e3 : 0.2f * e3;
        float w0 = __expf(e0), w1 = __expf(e1), w2 = __expf(e2), w3 = __expf(e3);
        dsum += (w0 + w1) + (w2 + w3);
        a0 = fmaf(w0, va0.x, a0); a1 = fmaf(w0, va0.y, a1);
        a2 = fmaf(w0, va0.z, a2); a3 = fmaf(w0, va0.w, a3);
        a4 = fmaf(w0, vb0.x, a4); a5 = fmaf(w0, vb0.y, a5);
        a6 = fmaf(w0, vb0.z, a6); a7 = fmaf(w0, vb0.w, a7);
        a0 = fmaf(w1, va1.x, a0); a1 = fmaf(w1, va1.y, a1);
        a2 = fmaf(w1, va1.z, a2); a3 = fmaf(w1, va1.w, a3);
        a4 = fmaf(w1, vb1.x, a4); a5 = fmaf(w1, vb1.y, a5);
        a6 = fmaf(w1, vb1.z, a6); a7 = fmaf(w1, vb1.w, a7);
        a0 = fmaf(w2, va2.x, a0); a1 = fmaf(w2, va2.y, a1);
        a2 = fmaf(w2, va2.z, a2); a3 = fmaf(w2, va2.w, a3);
        a4 = fmaf(w2, vb2.x, a4); a5 = fmaf(w2, vb2.y, a5);
        a6 = fmaf(w2, vb2.z, a6); a7 = fmaf(w2, vb2.w, a7);
        a0 = fmaf(w3, va3.x, a0); a1 = fmaf(w3, va3.y, a1);
        a2 = fmaf(w3, va3.z, a2); a3 = fmaf(w3, va3.w, a3);
        a4 = fmaf(w3, vb3.x, a4); a5 = fmaf(w3, vb3.y, a5);
        a6 = fmaf(w3, vb3.z, a6); a7 = fmaf(w3, vb3.w, a7);
    }
    for (; i < end; i++) {
        int s = g_csr[i];
        float e = g_als[s * HEADS + hh] + ald;
        e = (e > 0.f) ? e : 0.2f * e;
        float w = __expf(e);
        float4 va = g_z[s * (ZW/4) + zoff];
        float4 vb = g_z[s * (ZW/4) + zoff + 1];
        dsum += w;
        a0 = fmaf(w, va.x, a0); a1 = fmaf(w, va.y, a1);
        a2 = fmaf(w, va.z, a2); a3 = fmaf(w, va.w, a3);
        a4 = fmaf(w, vb.x, a4); a5 = fmaf(w, vb.y, a5);
        a6 = fmaf(w, vb.z, a6); a7 = fmaf(w, vb.w, a7);
    }
    float inv = 1.f / (dsum + 1e-16f);
    a0*=inv; a1*=inv; a2*=inv; a3*=inv; a4*=inv; a5*=inv; a6*=inv; a7*=inv;

    #pragma unroll
    for (int m = 8; m <= 16; m <<= 1) {
        a0 += __shfl_xor_sync(0xffffffffu, a0, m);
        a1 += __shfl_xor_sync(0xffffffffu, a1, m);
        a2 += __shfl_xor_sync(0xffffffffu, a2, m);
        a3 += __shfl_xor_sync(0xffffffffu, a3, m);
        a4 += __shfl_xor_sync(0xffffffffu, a4, m);
        a5 += __shfl_xor_sync(0xffffffffu, a5, m);
        a6 += __shfl_xor_sync(0xffffffffu, a6, m);
        a7 += __shfl_xor_sync(0xffffffffu, a7, m);
    }
    if (hh == 0) {
        int fb = fg * 8;
        float* o = g_h + (size_t)(cur ^ 1) * NPAD * HID + (size_t)n * HID + fb;
        o[0] = fmaxf(0.25f * a0 + bg[fb + 0], 0.f);
        o[1] = fmaxf(0.25f * a1 + bg[fb + 1], 0.f);
        o[2] = fmaxf(0.25f * a2 + bg[fb + 2], 0.f);
        o[3] = fmaxf(0.25f * a3 + bg[fb + 3], 0.f);
        o[4] = fmaxf(0.25f * a4 + bg[fb + 4], 0.f);
        o[5] = fmaxf(0.25f * a5 + bg[fb + 5], 0.f);
        o[6] = fmaxf(0.25f * a6 + bg[fb + 6], 0.f);
        o[7] = fmaxf(0.25f * a7 + bg[fb + 7], 0.f);
    }
}

// ---------------- global mean pool --------------------------------------------
__global__ void k_pool(const int* __restrict__ batch, int cur) {
    __shared__ int s_lo, s_hi;
    __shared__ float red[256];
    int g = blockIdx.x;
    if (threadIdx.x == 0) {
        int lo = 0, hi = NNODES;
        while (lo < hi) { int m = (lo + hi) >> 1; if (batch[m] < g) lo = m + 1; else hi = m; }
        s_lo = lo;
        lo = 0; hi = NNODES;
        while (lo < hi) { int m = (lo + hi) >> 1; if (batch[m] < g + 1) lo = m + 1; else hi = m; }
        s_hi = lo;
    }
    __syncthreads();
    int lo = s_lo, hi = s_hi;
    int f = threadIdx.x & 63, r = threadIdx.x >> 6;
    const float* h = g_h + (size_t)cur * NPAD * HID;
    float acc = 0.f;
    for (int n = lo + r; n < hi; n += 4) acc += h[(size_t)n * HID + f];
    red[threadIdx.x] = acc;
    __syncthreads();
    if (threadIdx.x < 64) {
        float v = red[f] + red[64 + f] + red[128 + f] + red[192 + f];
        float cnt = (float)max(hi - lo, 1);
        g_hg[g * HID + f] = v / cnt;
    }
}

// ---------------- final FC (2 outputs per thread) ------------------------------
__global__ void __launch_bounds__(256) k_fc(const float* __restrict__ Wfc,
                                            const float* __restrict__ bfc,
                                            float* __restrict__ out) {
    __shared__ float hg[NG * HID];
    int t = threadIdx.x;
    for (int i = t; i < NG * HID; i += 256) hg[i] = g_hg[i];
    __syncthreads();
    int o2 = blockIdx.x * 256 + t;
    if (o2 >= OUTF / 2) return;
    const float2* W2 = (const float2*)Wfc;
    float2 b2 = ((const float2*)bfc)[o2];
    float acc0[NG], acc1[NG];
    #pragma unroll
    for (int g = 0; g < NG; g++) { acc0[g] = b2.x; acc1[g] = b2.y; }
    for (int f = 0; f < HID; f++) {
        float2 w = W2[(size_t)f * (OUTF / 2) + o2];
        #pragma unroll
        for (int g = 0; g < NG; g++) {
            float hv = hg[g * HID + f];
            acc0[g] = fmaf(hv, w.x, acc0[g]);
            acc1[g] = fmaf(hv, w.y, acc1[g]);
        }
    }
    float2* out2 = (float2*)out;
    #pragma unroll
    for (int g = 0; g < NG; g++)
        out2[(size_t)g * (OUTF / 2) + o2] = make_float2(acc0[g], acc1[g]);
}

// ---------------- launch --------------------------------------------------------
extern "C" void kernel_launch(void* const* d_in, const int* in_sizes, int n_in,
                              void* d_out, int out_size) {
    const float* x     = (const float*)d_in[0];
    const int*   ei    = (const int*)d_in[1];
    const int*   batch = (const int*)d_in[3];
    const float* W_emb = (const float*)d_in[4];
    const float* b_emb = (const float*)d_in[5];
    const float* W_gat = (const float*)d_in[6];
    const float* a_src = (const float*)d_in[7];
    const float* a_dst = (const float*)d_in[8];
    const float* b_gat = (const float*)d_in[9];
    const float* W_fc  = (const float*)d_in[10];
    const float* b_fc  = (const float*)d_in[11];
    float* out = (float*)d_out;

    // launch #4 = k_z (ncu capture window)
    k_init_deg<<<NBLK, 256>>>();
    k_count<<<(NEDGES + 255) / 256, 256>>>(ei);
    k_emb<<<NTILES, 64>>>(x, W_emb, b_emb);
    k_z<<<NZBLK, 256>>>(W_gat, a_src, a_dst, 0);
    k_bsum<<<NBLK, 256>>>();
    k_bscan<<<1, 256>>>();
    k_offsets<<<NBLK, 256>>>();
    k_scatter<<<(NEDGES + 255) / 256, 256>>>(ei);
    k_agg<<<(NNODES * 32 + 255) / 256, 256>>>(b_gat, 0);

    int cur = 1;
    for (int l = 1; l < 3; l++) {
        k_z<<<NZBLK, 256>>>(W_gat + (size_t)l * HID * ZW,
                            a_src + (size_t)l * HEADS * HID,
                            a_dst + (size_t)l * HEADS * HID, cur);
        k_agg<<<(NNODES * 32 + 255) / 256, 256>>>(b_gat + (size_t)l * HID, cur);
        cur ^= 1;
    }

    k_pool<<<NG, 256>>>(batch, cur);
    k_fc<<<(OUTF / 2 + 255) / 256, 256>>>(W_fc, b_fc, out);
}

// round 8
// speedup vs baseline: 2.2862x; 1.2336x over previous
#include <cuda_runtime.h>
#include <cuda_bf16.h>
#include <cuda_fp16.h>
#include <math.h>

typedef unsigned long long ull;

#define NNODES 50000
#define NEDGES 500000
#define ETOT   (NEDGES + NNODES)
#define INF    128
#define HID    64
#define HEADS  4
#define ZW     (HEADS * HID)       // 256
#define NG     16
#define OUTF   326000
#define NT     32                  // emb node tile
#define NPAD   50048               // multiple of 64
#define NTILES (NPAD / NT)         // 1564
#define NZBLK  (NPAD / 64)         // 782
#define NBLK   196                 // ceil(NNODES/256)

#define FMA2(d,a,b,c) asm("fma.rn.f32x2 %0, %1, %2, %3;" : "=l"(d) : "l"(a), "l"(b), "l"(c))
#define PK2(d,lo,hi)  asm("mov.b64 %0, {%1, %2};" : "=l"(d) : "f"(lo), "f"(hi))
#define UPK2(lo,hi,s) asm("mov.b64 {%0, %1}, %2;" : "=f"(lo), "=f"(hi) : "l"(s))

// ---------------- scratch ----------------------------------------------------
__device__ float  g_h[2 * NPAD * HID];
__device__ __align__(16) __half g_zh[(size_t)NPAD * ZW];   // z in fp16 (512B/row)
__device__ float  g_als[NPAD * HEADS];
__device__ float  g_ald[NPAD * HEADS];
__device__ int    g_deg[NNODES];
__device__ int    g_off[NNODES + 1];
__device__ int    g_cur[NNODES];
__device__ int    g_csr[ETOT];
__device__ int    g_bsum[256];
__device__ int    g_boff[256];
__device__ float  g_hg[NG * HID];

// ---------------- CSR build --------------------------------------------------
__global__ void k_init_deg() {
    int i = blockIdx.x * blockDim.x + threadIdx.x;
    if (i < NNODES) g_deg[i] = 1;            // self-loop
}

__global__ void k_count(const int* __restrict__ ei) {
    int e = blockIdx.x * blockDim.x + threadIdx.x;
    if (e >= NEDGES) return;
    atomicAdd(&g_deg[ei[NEDGES + e]], 1);
}

__global__ void k_bsum() {
    __shared__ int sm[256];
    int i = blockIdx.x * 256 + threadIdx.x;
    sm[threadIdx.x] = (i < NNODES) ? g_deg[i] : 0;
    __syncthreads();
    for (int o = 128; o; o >>= 1) {
        if (threadIdx.x < o) sm[threadIdx.x] += sm[threadIdx.x + o];
        __syncthreads();
    }
    if (threadIdx.x == 0) g_bsum[blockIdx.x] = sm[0];
}

__global__ void k_bscan() {
    __shared__ int sm[512];
    int t = threadIdx.x;
    sm[t] = 0;
    sm[256 + t] = (t < NBLK) ? g_bsum[t] : 0;
    __syncthreads();
    for (int d = 1; d < 256; d <<= 1) {
        int v = sm[256 + t - d];
        __syncthreads();
        sm[256 + t] += v;
        __syncthreads();
    }
    g_boff[t] = sm[255 + t];
    if (t == 0) g_off[NNODES] = ETOT;
}

__global__ void k_offsets() {
    __shared__ int sm[512];
    int t = threadIdx.x;
    int i = blockIdx.x * 256 + t;
    int d = (i < NNODES) ? g_deg[i] : 0;
    sm[t] = 0;
    sm[256 + t] = d;
    __syncthreads();
    for (int dd = 1; dd < 256; dd <<= 1) {
        int v = sm[256 + t - dd];
        __syncthreads();
        sm[256 + t] += v;
        __syncthreads();
    }
    if (i < NNODES) {
        int run = g_boff[blockIdx.x] + sm[255 + t];
        g_off[i] = run;
        g_csr[run] = i;
        g_cur[i] = run + 1;
    }
}

__global__ void k_scatter(const int* __restrict__ ei) {
    int e = blockIdx.x * blockDim.x + threadIdx.x;
    if (e >= NEDGES) return;
    int s = ei[e];
    int p = atomicAdd(&g_cur[ei[NEDGES + e]], 1);
    g_csr[p] = s;
}

// ---------------- embedding GEMM ----------------------------------------------
__global__ void __launch_bounds__(64) k_emb(const float* __restrict__ x,
                                            const float* __restrict__ W,
                                            const float* __restrict__ b) {
    __shared__ float xs[INF * 36];
    int k = threadIdx.x;
    int n0 = blockIdx.x * NT;
    float wc[INF];
    #pragma unroll
    for (int f = 0; f < INF; f++) wc[f] = W[f * HID + k];
    #pragma unroll
    for (int j = 0; j < 16; j++) {
        int idx = k + 64 * j;
        int nl = idx >> 5;
        int fq = idx & 31;
        int n = n0 + nl;
        float4 v = (n < NNODES) ? *(const float4*)&x[(size_t)n * INF + fq * 4]
                                : make_float4(0.f, 0.f, 0.f, 0.f);
        xs[(fq * 4 + 0) * 36 + nl] = v.x;
        xs[(fq * 4 + 1) * 36 + nl] = v.y;
        xs[(fq * 4 + 2) * 36 + nl] = v.z;
        xs[(fq * 4 + 3) * 36 + nl] = v.w;
    }
    __syncthreads();
    float acc[NT];
    #pragma unroll
    for (int j = 0; j < NT; j++) acc[j] = 0.f;
    #pragma unroll 4
    for (int f = 0; f < INF; f++) {
        const float4* row = (const float4*)&xs[f * 36];
        float w = wc[f];
        #pragma unroll
        for (int q = 0; q < 8; q++) {
            float4 hv = row[q];
            acc[q * 4 + 0] = fmaf(hv.x, w, acc[q * 4 + 0]);
            acc[q * 4 + 1] = fmaf(hv.y, w, acc[q * 4 + 1]);
            acc[q * 4 + 2] = fmaf(hv.z, w, acc[q * 4 + 2]);
            acc[q * 4 + 3] = fmaf(hv.w, w, acc[q * 4 + 3]);
        }
    }
    float bk = b[k];
    #pragma unroll
    for (int j = 0; j < NT; j++)
        g_h[(size_t)(n0 + j) * HID + k] = acc[j] + bk;
}

// ---------------- z GEMM (8x8 reg tile, f32x2) + fused attention logits -------
__global__ void __launch_bounds__(256, 2) k_z(const float* __restrict__ Wg,
                                              const float* __restrict__ asrc,
                                              const float* __restrict__ adst,
                                              int cur) {
    __shared__ float4 ws4[32 * 64];
    __shared__ __align__(16) float hs[32 * 68];
    int tid = threadIdx.x;
    int n0 = blockIdx.x * 64;
    int ni = tid >> 5;
    int cj = tid & 31;
    const float* h = g_h + (size_t)cur * NPAD * HID;

    ull acc[8][4];
    #pragma unroll
    for (int c = 0; c < 8; c++)
        #pragma unroll
        for (int p = 0; p < 4; p++) acc[c][p] = 0ull;

    #pragma unroll
    for (int ch = 0; ch < 2; ch++) {
        int fb = ch * 32;
        __syncthreads();
        const float4* Wg4 = (const float4*)(Wg + fb * ZW);
        #pragma unroll
        for (int j = 0; j < 8; j++) ws4[tid + 256 * j] = Wg4[tid + 256 * j];
        #pragma unroll
        for (int j = 0; j < 2; j++) {
            int idx = tid + 256 * j;
            int nl = idx & 63;
            int fq = idx >> 6;
            float4 v = *(const float4*)&h[(size_t)(n0 + nl) * HID + fb + fq * 4];
            hs[(fq * 4 + 0) * 68 + nl] = v.x;
            hs[(fq * 4 + 1) * 68 + nl] = v.y;
            hs[(fq * 4 + 2) * 68 + nl] = v.z;
            hs[(fq * 4 + 3) * 68 + nl] = v.w;
        }
        __syncthreads();
        #pragma unroll 2
        for (int f = 0; f < 32; f++) {
            float4 ha = *(const float4*)&hs[f * 68 + ni * 8];
            float4 hb = *(const float4*)&hs[f * 68 + ni * 8 + 4];
            float4 wa = ws4[f * 64 + cj * 2];
            float4 wb = ws4[f * 64 + cj * 2 + 1];
            ull hp[4];
            PK2(hp[0], ha.x, ha.y); PK2(hp[1], ha.z, ha.w);
            PK2(hp[2], hb.x, hb.y); PK2(hp[3], hb.z, hb.w);
            float wv[8] = {wa.x, wa.y, wa.z, wa.w, wb.x, wb.y, wb.z, wb.w};
            #pragma unroll
            for (int c = 0; c < 8; c++) {
                ull wd; PK2(wd, wv[c], wv[c]);
                #pragma unroll
                for (int p = 0; p < 4; p++) FMA2(acc[c][p], hp[p], wd, acc[c][p]);
            }
        }
    }

    // ---- fused attention logits ----
    float4 sa0 = *(const float4*)&asrc[cj * 8];
    float4 sa1 = *(const float4*)&asrc[cj * 8 + 4];
    float4 sd0 = *(const float4*)&adst[cj * 8];
    float4 sd1 = *(const float4*)&adst[cj * 8 + 4];
    float sav[8] = {sa0.x, sa0.y, sa0.z, sa0.w, sa1.x, sa1.y, sa1.z, sa1.w};
    float sdv[8] = {sd0.x, sd0.y, sd0.z, sd0.w, sd1.x, sd1.y, sd1.z, sd1.w};
    ull ds[4] = {0, 0, 0, 0}, dd[4] = {0, 0, 0, 0};
    #pragma unroll
    for (int c = 0; c < 8; c++) {
        ull t;
        PK2(t, sav[c], sav[c]);
        #pragma unroll
        for (int p = 0; p < 4; p++) FMA2(ds[p], acc[c][p], t, ds[p]);
        PK2(t, sdv[c], sdv[c]);
        #pragma unroll
        for (int p = 0; p < 4; p++) FMA2(dd[p], acc[c][p], t, dd[p]);
    }
    float dsl[8], ddl[8];
    #pragma unroll
    for (int p = 0; p < 4; p++) {
        UPK2(dsl[2 * p], dsl[2 * p + 1], ds[p]);
        UPK2(ddl[2 * p], ddl[2 * p + 1], dd[p]);
    }
    #pragma unroll
    for (int m = 0; m < 8; m++) {
        #pragma unroll
        for (int o = 1; o <= 4; o <<= 1) {
            dsl[m] += __shfl_xor_sync(0xffffffffu, dsl[m], o);
            ddl[m] += __shfl_xor_sync(0xffffffffu, ddl[m], o);
        }
    }
    if ((cj & 7) == 0) {
        int hh = cj >> 3;
        #pragma unroll
        for (int m = 0; m < 8; m++) {
            int n = n0 + ni * 8 + m;
            g_als[n * HEADS + hh] = dsl[m];
            g_ald[n * HEADS + hh] = ddl[m];
        }
    }

    // ---- store z tile as fp16 (row = 256 halves = 32 uint4) ----
    uint4* zh4 = (uint4*)g_zh;
    #pragma unroll
    for (int p = 0; p < 4; p++) {
        float lo[8], hi[8];
        #pragma unroll
        for (int c = 0; c < 8; c++) UPK2(lo[c], hi[c], acc[c][p]);
        __half2 pl[4], ph[4];
        #pragma unroll
        for (int q = 0; q < 4; q++) {
            pl[q] = __floats2half2_rn(lo[2 * q], lo[2 * q + 1]);
            ph[q] = __floats2half2_rn(hi[2 * q], hi[2 * q + 1]);
        }
        zh4[(size_t)(n0 + ni * 8 + 2 * p) * 32 + cj] = *(uint4*)pl;
        zh4[(size_t)(n0 + ni * 8 + 2 * p + 1) * 32 + cj] = *(uint4*)ph;
    }
}

// ---------------- per-dst aggregation (warp/node, fp16 z, 4-way unroll) ------
__global__ void __launch_bounds__(256) k_agg(const float* __restrict__ bg, int cur) {
    int wid = (blockIdx.x * blockDim.x + threadIdx.x) >> 5;
    if (wid >= NNODES) return;
    int n = wid;
    int lane = threadIdx.x & 31;
    int hh = lane >> 3;
    int fg = lane & 7;

    float ald = g_ald[n * HEADS + hh];
    float a0=0,a1=0,a2=0,a3=0,a4=0,a5=0,a6=0,a7=0;
    float dsum = 0.f;

    const uint4* zh4 = (const uint4*)g_zh;
    int zo = hh * 8 + fg;                    // uint4 offset within a 32-uint4 row
    int beg = g_off[n], end = g_off[n + 1];
    int i = beg;
    for (; i + 4 <= end; i += 4) {
        int s0 = g_csr[i], s1 = g_csr[i+1], s2 = g_csr[i+2], s3 = g_csr[i+3];
        float l0 = g_als[s0 * HEADS + hh];
        float l1 = g_als[s1 * HEADS + hh];
        float l2 = g_als[s2 * HEADS + hh];
        float l3 = g_als[s3 * HEADS + hh];
        uint4 v0 = zh4[(size_t)s0 * 32 + zo];
        uint4 v1 = zh4[(size_t)s1 * 32 + zo];
        uint4 v2 = zh4[(size_t)s2 * 32 + zo];
        uint4 v3 = zh4[(size_t)s3 * 32 + zo];
        float e0 = l0 + ald, e1 = l1 + ald, e2 = l2 + ald, e3 = l3 + ald;
        e0 = (e0 > 0.f) ? e0 : 0.2f * e0;
        e1 = (e1 > 0.f) ? e1 : 0.2f * e1;
        e2 = (e2 > 0.f) ? e2 : 0.2f * e2;
        e3 = (e3 > 0.f) ? e3 : 0.2f * e3;
        float w0 = __expf(e0), w1 = __expf(e1), w2 = __expf(e2), w3 = __expf(e3);
        dsum += (w0 + w1) + (w2 + w3);
        {
            const __half2* p = (const __half2*)&v0;
            float2 q0 = __half22float2(p[0]), q1 = __half22float2(p[1]);
            float2 q2 = __half22float2(p[2]), q3 = __half22float2(p[3]);
            a0 = fmaf(w0, q0.x, a0); a1 = fmaf(w0, q0.y, a1);
            a2 = fmaf(w0, q1.x, a2); a3 = fmaf(w0, q1.y, a3);
            a4 = fmaf(w0, q2.x, a4); a5 = fmaf(w0, q2.y, a5);
            a6 = fmaf(w0, q3.x, a6); a7 = fmaf(w0, q3.y, a7);
        }
        {
            const __half2* p = (const __half2*)&v1;
            float2 q0 = __half22float2(p[0]), q1 = __half22float2(p[1]);
            float2 q2 = __half22float2(p[2]), q3 = __half22float2(p[3]);
            a0 = fmaf(w1, q0.x, a0); a1 = fmaf(w1, q0.y, a1);
            a2 = fmaf(w1, q1.x, a2); a3 = fmaf(w1, q1.y, a3);
            a4 = fmaf(w1, q2.x, a4); a5 = fmaf(w1, q2.y, a5);
            a6 = fmaf(w1, q3.x, a6); a7 = fmaf(w1, q3.y, a7);
        }
        {
            const __half2* p = (const __half2*)&v2;
            float2 q0 = __half22float2(p[0]), q1 = __half22float2(p[1]);
            float2 q2 = __half22float2(p[2]), q3 = __half22float2(p[3]);
            a0 = fmaf(w2, q0.x, a0); a1 = fmaf(w2, q0.y, a1);
            a2 = fmaf(w2, q1.x, a2); a3 = fmaf(w2, q1.y, a3);
            a4 = fmaf(w2, q2.x, a4); a5 = fmaf(w2, q2.y, a5);
            a6 = fmaf(w2, q3.x, a6); a7 = fmaf(w2, q3.y, a7);
        }
        {
            const __half2* p = (const __half2*)&v3;
            float2 q0 = __half22float2(p[0]), q1 = __half22float2(p[1]);
            float2 q2 = __half22float2(p[2]), q3 = __half22float2(p[3]);
            a0 = fmaf(w3, q0.x, a0); a1 = fmaf(w3, q0.y, a1);
            a2 = fmaf(w3, q1.x, a2); a3 = fmaf(w3, q1.y, a3);
            a4 = fmaf(w3, q2.x, a4); a5 = fmaf(w3, q2.y, a5);
            a6 = fmaf(w3, q3.x, a6); a7 = fmaf(w3, q3.y, a7);
        }
    }
    for (; i < end; i++) {
        int s = g_csr[i];
        float e = g_als[s * HEADS + hh] + ald;
        e = (e > 0.f) ? e : 0.2f * e;
        float w = __expf(e);
        uint4 v = zh4[(size_t)s * 32 + zo];
        const __half2* p = (const __half2*)&v;
        float2 q0 = __half22float2(p[0]), q1 = __half22float2(p[1]);
        float2 q2 = __half22float2(p[2]), q3 = __half22float2(p[3]);
        dsum += w;
        a0 = fmaf(w, q0.x, a0); a1 = fmaf(w, q0.y, a1);
        a2 = fmaf(w, q1.x, a2); a3 = fmaf(w, q1.y, a3);
        a4 = fmaf(w, q2.x, a4); a5 = fmaf(w, q2.y, a5);
        a6 = fmaf(w, q3.x, a6); a7 = fmaf(w, q3.y, a7);
    }
    float inv = 1.f / (dsum + 1e-16f);
    a0*=inv; a1*=inv; a2*=inv; a3*=inv; a4*=inv; a5*=inv; a6*=inv; a7*=inv;

    #pragma unroll
    for (int m = 8; m <= 16; m <<= 1) {
        a0 += __shfl_xor_sync(0xffffffffu, a0, m);
        a1 += __shfl_xor_sync(0xffffffffu, a1, m);
        a2 += __shfl_xor_sync(0xffffffffu, a2, m);
        a3 += __shfl_xor_sync(0xffffffffu, a3, m);
        a4 += __shfl_xor_sync(0xffffffffu, a4, m);
        a5 += __shfl_xor_sync(0xffffffffu, a5, m);
        a6 += __shfl_xor_sync(0xffffffffu, a6, m);
        a7 += __shfl_xor_sync(0xffffffffu, a7, m);
    }
    if (hh == 0) {
        int fb = fg * 8;
        float* o = g_h + (size_t)(cur ^ 1) * NPAD * HID + (size_t)n * HID + fb;
        o[0] = fmaxf(0.25f * a0 + bg[fb + 0], 0.f);
        o[1] = fmaxf(0.25f * a1 + bg[fb + 1], 0.f);
        o[2] = fmaxf(0.25f * a2 + bg[fb + 2], 0.f);
        o[3] = fmaxf(0.25f * a3 + bg[fb + 3], 0.f);
        o[4] = fmaxf(0.25f * a4 + bg[fb + 4], 0.f);
        o[5] = fmaxf(0.25f * a5 + bg[fb + 5], 0.f);
        o[6] = fmaxf(0.25f * a6 + bg[fb + 6], 0.f);
        o[7] = fmaxf(0.25f * a7 + bg[fb + 7], 0.f);
    }
}

// ---------------- global mean pool --------------------------------------------
__global__ void k_pool(const int* __restrict__ batch, int cur) {
    __shared__ int s_lo, s_hi;
    __shared__ float red[256];
    int g = blockIdx.x;
    if (threadIdx.x == 0) {
        int lo = 0, hi = NNODES;
        while (lo < hi) { int m = (lo + hi) >> 1; if (batch[m] < g) lo = m + 1; else hi = m; }
        s_lo = lo;
        lo = 0; hi = NNODES;
        while (lo < hi) { int m = (lo + hi) >> 1; if (batch[m] < g + 1) lo = m + 1; else hi = m; }
        s_hi = lo;
    }
    __syncthreads();
    int lo = s_lo, hi = s_hi;
    int f = threadIdx.x & 63, r = threadIdx.x >> 6;
    const float* h = g_h + (size_t)cur * NPAD * HID;
    float acc = 0.f;
    for (int n = lo + r; n < hi; n += 4) acc += h[(size_t)n * HID + f];
    red[threadIdx.x] = acc;
    __syncthreads();
    if (threadIdx.x < 64) {
        float v = red[f] + red[64 + f] + red[128 + f] + red[192 + f];
        float cnt = (float)max(hi - lo, 1);
        g_hg[g * HID + f] = v / cnt;
    }
}

// ---------------- final FC (2 outputs per thread) ------------------------------
__global__ void __launch_bounds__(256) k_fc(const float* __restrict__ Wfc,
                                            const float* __restrict__ bfc,
                                            float* __restrict__ out) {
    __shared__ float hg[NG * HID];
    int t = threadIdx.x;
    for (int i = t; i < NG * HID; i += 256) hg[i] = g_hg[i];
    __syncthreads();
    int o2 = blockIdx.x * 256 + t;
    if (o2 >= OUTF / 2) return;
    const float2* W2 = (const float2*)Wfc;
    float2 b2 = ((const float2*)bfc)[o2];
    float acc0[NG], acc1[NG];
    #pragma unroll
    for (int g = 0; g < NG; g++) { acc0[g] = b2.x; acc1[g] = b2.y; }
    for (int f = 0; f < HID; f++) {
        float2 w = W2[(size_t)f * (OUTF / 2) + o2];
        #pragma unroll
        for (int g = 0; g < NG; g++) {
            float hv = hg[g * HID + f];
            acc0[g] = fmaf(hv, w.x, acc0[g]);
            acc1[g] = fmaf(hv, w.y, acc1[g]);
        }
    }
    float2* out2 = (float2*)out;
    #pragma unroll
    for (int g = 0; g < NG; g++)
        out2[(size_t)g * (OUTF / 2) + o2] = make_float2(acc0[g], acc1[g]);
}

// ---------------- launch --------------------------------------------------------
extern "C" void kernel_launch(void* const* d_in, const int* in_sizes, int n_in,
                              void* d_out, int out_size) {
    const float* x     = (const float*)d_in[0];
    const int*   ei    = (const int*)d_in[1];
    const int*   batch = (const int*)d_in[3];
    const float* W_emb = (const float*)d_in[4];
    const float* b_emb = (const float*)d_in[5];
    const float* W_gat = (const float*)d_in[6];
    const float* a_src = (const float*)d_in[7];
    const float* a_dst = (const float*)d_in[8];
    const float* b_gat = (const float*)d_in[9];
    const float* W_fc  = (const float*)d_in[10];
    const float* b_fc  = (const float*)d_in[11];
    float* out = (float*)d_out;

    // launch #4 = k_emb (ncu capture window)
    k_init_deg<<<NBLK, 256>>>();
    k_count<<<(NEDGES + 255) / 256, 256>>>(ei);
    k_bsum<<<NBLK, 256>>>();
    k_emb<<<NTILES, 64>>>(x, W_emb, b_emb);
    k_bscan<<<1, 256>>>();
    k_offsets<<<NBLK, 256>>>();
    k_scatter<<<(NEDGES + 255) / 256, 256>>>(ei);
    k_z<<<NZBLK, 256>>>(W_gat, a_src, a_dst, 0);
    k_agg<<<(NNODES * 32 + 255) / 256, 256>>>(b_gat, 0);

    int cur = 1;
    for (int l = 1; l < 3; l++) {
        k_z<<<NZBLK, 256>>>(W_gat + (size_t)l * HID * ZW,
                            a_src + (size_t)l * HEADS * HID,
                            a_dst + (size_t)l * HEADS * HID, cur);
        k_agg<<<(NNODES * 32 + 255) / 256, 256>>>(b_gat + (size_t)l * HID, cur);
        cur ^= 1;
    }

    k_pool<<<NG, 256>>>(batch, cur);
    k_fc<<<(OUTF / 2 + 255) / 256, 256>>>(W_fc, b_fc, out);
}

// round 9
// speedup vs baseline: 2.3601x; 1.0323x over previous
#include <cuda_runtime.h>
#include <cuda_bf16.h>
#include <cuda_fp16.h>
#include <math.h>

typedef unsigned long long ull;

#define NNODES 50000
#define NEDGES 500000
#define ETOT   (NEDGES + NNODES)
#define INF    128
#define HID    64
#define HEADS  4
#define ZW     (HEADS * HID)       // 256
#define NG     16
#define OUTF   326000
#define NPAD   50048               // multiple of 128
#define NEBLK  (NPAD / 128)        // 391 emb tiles
#define NZBLK  (NPAD / 64)         // 782
#define NBLK   196                 // ceil(NNODES/256)

#define FMA2(d,a,b,c) asm("fma.rn.f32x2 %0, %1, %2, %3;" : "=l"(d) : "l"(a), "l"(b), "l"(c))
#define PK2(d,lo,hi)  asm("mov.b64 %0, {%1, %2};" : "=l"(d) : "f"(lo), "f"(hi))
#define UPK2(lo,hi,s) asm("mov.b64 {%0, %1}, %2;" : "=f"(lo), "=f"(hi) : "l"(s))

// ---------------- scratch ----------------------------------------------------
__device__ float  g_h[2 * NPAD * HID];
__device__ __align__(16) __half g_zh[(size_t)NPAD * ZW];   // z in fp16
__device__ float  g_als[NPAD * HEADS];
__device__ float  g_ald[NPAD * HEADS];
__device__ int    g_deg[NNODES];            // real-edge indegree (self-loop added analytically)
__device__ int    g_off[NNODES + 1];
__device__ int    g_cur[NNODES];
__device__ int    g_csr[ETOT];
__device__ int    g_bsum[256];
__device__ int    g_boff[256];
__device__ float  g_hg[NG * HID];

// ---------------- CSR build --------------------------------------------------
__global__ void k_count(const int* __restrict__ ei) {
    int e = blockIdx.x * blockDim.x + threadIdx.x;
    if (e >= NEDGES) return;
    atomicAdd(&g_deg[ei[NEDGES + e]], 1);
}

__global__ void k_bsum() {
    __shared__ int sm[256];
    int i = blockIdx.x * 256 + threadIdx.x;
    sm[threadIdx.x] = (i < NNODES) ? (g_deg[i] + 1) : 0;   // +1 self-loop
    __syncthreads();
    for (int o = 128; o; o >>= 1) {
        if (threadIdx.x < o) sm[threadIdx.x] += sm[threadIdx.x + o];
        __syncthreads();
    }
    if (threadIdx.x == 0) g_bsum[blockIdx.x] = sm[0];
}

__global__ void k_bscan() {
    __shared__ int sm[512];
    int t = threadIdx.x;
    sm[t] = 0;
    sm[256 + t] = (t < NBLK) ? g_bsum[t] : 0;
    __syncthreads();
    for (int d = 1; d < 256; d <<= 1) {
        int v = sm[256 + t - d];
        __syncthreads();
        sm[256 + t] += v;
        __syncthreads();
    }
    g_boff[t] = sm[255 + t];
    if (t == 0) g_off[NNODES] = ETOT;
}

__global__ void k_offsets() {
    __shared__ int sm[512];
    int t = threadIdx.x;
    int i = blockIdx.x * 256 + t;
    int d = (i < NNODES) ? (g_deg[i] + 1) : 0;             // +1 self-loop
    sm[t] = 0;
    sm[256 + t] = d;
    __syncthreads();
    for (int dd = 1; dd < 256; dd <<= 1) {
        int v = sm[256 + t - dd];
        __syncthreads();
        sm[256 + t] += v;
        __syncthreads();
    }
    if (i < NNODES) {
        int run = g_boff[blockIdx.x] + sm[255 + t];
        g_off[i] = run;
        g_csr[run] = i;                                    // self-loop first
        g_cur[i] = run + 1;
    }
}

__global__ void k_scatter(const int* __restrict__ ei) {
    int e = blockIdx.x * blockDim.x + threadIdx.x;
    if (e >= NEDGES) return;
    int s = ei[e];
    int p = atomicAdd(&g_cur[ei[NEDGES + e]], 1);
    g_csr[p] = s;
}

// ---------------- embedding GEMM: h0 = x @ W_emb + b  (8c x 4n reg tile) ------
// block: 128 nodes x 64 cols, 256 threads; K=128 in 4 chunks of 32.
__global__ void __launch_bounds__(256, 3) k_emb(const float* __restrict__ x,
                                                const float* __restrict__ W,
                                                const float* __restrict__ b) {
    __shared__ __align__(16) float xs[32 * 132];   // [32f][128n pad] 16.9KB
    __shared__ float4 ws4[32 * 16];                // [32f][64c]      8KB
    int tid = threadIdx.x;
    int n0 = blockIdx.x * 128;
    int ni = tid >> 5;
    int cj = tid & 31;
    int nsub = ni * 16 + (cj >> 3) * 4;            // 4 nodes
    int cb = (cj & 7) * 8;                         // 8 cols

    ull acc[8][2];
    #pragma unroll
    for (int c = 0; c < 8; c++) { acc[c][0] = 0ull; acc[c][1] = 0ull; }

    #pragma unroll
    for (int ch = 0; ch < 4; ch++) {
        int fb = ch * 32;
        __syncthreads();
        const float4* Wg4 = (const float4*)(W + fb * HID);
        ws4[tid] = Wg4[tid];
        ws4[tid + 256] = Wg4[tid + 256];
        #pragma unroll
        for (int j = 0; j < 4; j++) {
            int idx = tid + 256 * j;               // 0..1023
            int nl = idx >> 3;                     // node 0..127
            int fq = idx & 7;                      // f quad
            int n = n0 + nl;
            float4 v = (n < NNODES) ? *(const float4*)&x[(size_t)n * INF + fb + fq * 4]
                                    : make_float4(0.f, 0.f, 0.f, 0.f);
            xs[(fq * 4 + 0) * 132 + nl] = v.x;
            xs[(fq * 4 + 1) * 132 + nl] = v.y;
            xs[(fq * 4 + 2) * 132 + nl] = v.z;
            xs[(fq * 4 + 3) * 132 + nl] = v.w;
        }
        __syncthreads();
        #pragma unroll 4
        for (int f = 0; f < 32; f++) {
            float4 hv = *(const float4*)&xs[f * 132 + nsub];
            float4 wa = ws4[f * 16 + (cj & 7) * 2];
            float4 wb = ws4[f * 16 + (cj & 7) * 2 + 1];
            ull hp0, hp1;
            PK2(hp0, hv.x, hv.y);
            PK2(hp1, hv.z, hv.w);
            float wv[8] = {wa.x, wa.y, wa.z, wa.w, wb.x, wb.y, wb.z, wb.w};
            #pragma unroll
            for (int c = 0; c < 8; c++) {
                ull wd; PK2(wd, wv[c], wv[c]);
                FMA2(acc[c][0], hp0, wd, acc[c][0]);
                FMA2(acc[c][1], hp1, wd, acc[c][1]);
            }
        }
    }

    float4 b0 = *(const float4*)&b[cb];
    float4 b1 = *(const float4*)&b[cb + 4];
    float bv[8] = {b0.x, b0.y, b0.z, b0.w, b1.x, b1.y, b1.z, b1.w};
    #pragma unroll
    for (int p = 0; p < 2; p++) {
        float lo[8], hi[8];
        #pragma unroll
        for (int c = 0; c < 8; c++) {
            UPK2(lo[c], hi[c], acc[c][p]);
            lo[c] += bv[c]; hi[c] += bv[c];
        }
        float* oa = g_h + (size_t)(n0 + nsub + 2 * p) * HID + cb;
        float* ob = oa + HID;
        ((float4*)oa)[0] = make_float4(lo[0], lo[1], lo[2], lo[3]);
        ((float4*)oa)[1] = make_float4(lo[4], lo[5], lo[6], lo[7]);
        ((float4*)ob)[0] = make_float4(hi[0], hi[1], hi[2], hi[3]);
        ((float4*)ob)[1] = make_float4(hi[4], hi[5], hi[6], hi[7]);
    }
}

// ---------------- z GEMM (8x8 reg tile, f32x2) + fused attention logits -------
__global__ void __launch_bounds__(256, 2) k_z(const float* __restrict__ Wg,
                                              const float* __restrict__ asrc,
                                              const float* __restrict__ adst,
                                              int cur) {
    __shared__ float4 ws4[32 * 64];
    __shared__ __align__(16) float hs[32 * 68];
    int tid = threadIdx.x;
    int n0 = blockIdx.x * 64;
    int ni = tid >> 5;
    int cj = tid & 31;
    const float* h = g_h + (size_t)cur * NPAD * HID;

    ull acc[8][4];
    #pragma unroll
    for (int c = 0; c < 8; c++)
        #pragma unroll
        for (int p = 0; p < 4; p++) acc[c][p] = 0ull;

    #pragma unroll
    for (int ch = 0; ch < 2; ch++) {
        int fb = ch * 32;
        __syncthreads();
        const float4* Wg4 = (const float4*)(Wg + fb * ZW);
        #pragma unroll
        for (int j = 0; j < 8; j++) ws4[tid + 256 * j] = Wg4[tid + 256 * j];
        #pragma unroll
        for (int j = 0; j < 2; j++) {
            int idx = tid + 256 * j;
            int nl = idx & 63;
            int fq = idx >> 6;
            float4 v = *(const float4*)&h[(size_t)(n0 + nl) * HID + fb + fq * 4];
            hs[(fq * 4 + 0) * 68 + nl] = v.x;
            hs[(fq * 4 + 1) * 68 + nl] = v.y;
            hs[(fq * 4 + 2) * 68 + nl] = v.z;
            hs[(fq * 4 + 3) * 68 + nl] = v.w;
        }
        __syncthreads();
        #pragma unroll 2
        for (int f = 0; f < 32; f++) {
            float4 ha = *(const float4*)&hs[f * 68 + ni * 8];
            float4 hb = *(const float4*)&hs[f * 68 + ni * 8 + 4];
            float4 wa = ws4[f * 64 + cj * 2];
            float4 wb = ws4[f * 64 + cj * 2 + 1];
            ull hp[4];
            PK2(hp[0], ha.x, ha.y); PK2(hp[1], ha.z, ha.w);
            PK2(hp[2], hb.x, hb.y); PK2(hp[3], hb.z, hb.w);
            float wv[8] = {wa.x, wa.y, wa.z, wa.w, wb.x, wb.y, wb.z, wb.w};
            #pragma unroll
            for (int c = 0; c < 8; c++) {
                ull wd; PK2(wd, wv[c], wv[c]);
                #pragma unroll
                for (int p = 0; p < 4; p++) FMA2(acc[c][p], hp[p], wd, acc[c][p]);
            }
        }
    }

    // ---- fused attention logits ----
    float4 sa0 = *(const float4*)&asrc[cj * 8];
    float4 sa1 = *(const float4*)&asrc[cj * 8 + 4];
    float4 sd0 = *(const float4*)&adst[cj * 8];
    float4 sd1 = *(const float4*)&adst[cj * 8 + 4];
    float sav[8] = {sa0.x, sa0.y, sa0.z, sa0.w, sa1.x, sa1.y, sa1.z, sa1.w};
    float sdv[8] = {sd0.x, sd0.y, sd0.z, sd0.w, sd1.x, sd1.y, sd1.z, sd1.w};
    ull ds[4] = {0, 0, 0, 0}, dd[4] = {0, 0, 0, 0};
    #pragma unroll
    for (int c = 0; c < 8; c++) {
        ull t;
        PK2(t, sav[c], sav[c]);
        #pragma unroll
        for (int p = 0; p < 4; p++) FMA2(ds[p], acc[c][p], t, ds[p]);
        PK2(t, sdv[c], sdv[c]);
        #pragma unroll
        for (int p = 0; p < 4; p++) FMA2(dd[p], acc[c][p], t, dd[p]);
    }
    float dsl[8], ddl[8];
    #pragma unroll
    for (int p = 0; p < 4; p++) {
        UPK2(dsl[2 * p], dsl[2 * p + 1], ds[p]);
        UPK2(ddl[2 * p], ddl[2 * p + 1], dd[p]);
    }
    #pragma unroll
    for (int m = 0; m < 8; m++) {
        #pragma unroll
        for (int o = 1; o <= 4; o <<= 1) {
            dsl[m] += __shfl_xor_sync(0xffffffffu, dsl[m], o);
            ddl[m] += __shfl_xor_sync(0xffffffffu, ddl[m], o);
        }
    }
    if ((cj & 7) == 0) {
        int hh = cj >> 3;
        #pragma unroll
        for (int m = 0; m < 8; m++) {
            int n = n0 + ni * 8 + m;
            g_als[n * HEADS + hh] = dsl[m];
            g_ald[n * HEADS + hh] = ddl[m];
        }
    }

    // ---- store z tile as fp16 ----
    uint4* zh4 = (uint4*)g_zh;
    #pragma unroll
    for (int p = 0; p < 4; p++) {
        float lo[8], hi[8];
        #pragma unroll
        for (int c = 0; c < 8; c++) UPK2(lo[c], hi[c], acc[c][p]);
        __half2 pl[4], ph[4];
        #pragma unroll
        for (int q = 0; q < 4; q++) {
            pl[q] = __floats2half2_rn(lo[2 * q], lo[2 * q + 1]);
            ph[q] = __floats2half2_rn(hi[2 * q], hi[2 * q + 1]);
        }
        zh4[(size_t)(n0 + ni * 8 + 2 * p) * 32 + cj] = *(uint4*)pl;
        zh4[(size_t)(n0 + ni * 8 + 2 * p + 1) * 32 + cj] = *(uint4*)ph;
    }
}

// ---------------- per-dst aggregation (warp/node, fp16 z, 4-way unroll) ------
__global__ void __launch_bounds__(256) k_agg(const float* __restrict__ bg, int cur) {
    int wid = (blockIdx.x * blockDim.x + threadIdx.x) >> 5;
    if (wid >= NNODES) return;
    int n = wid;
    int lane = threadIdx.x & 31;
    int hh = lane >> 3;
    int fg = lane & 7;

    float ald = g_ald[n * HEADS + hh];
    float a0=0,a1=0,a2=0,a3=0,a4=0,a5=0,a6=0,a7=0;
    float dsum = 0.f;

    const uint4* zh4 = (const uint4*)g_zh;
    int zo = hh * 8 + fg;
    int beg = g_off[n], end = g_off[n + 1];
    int i = beg;
    for (; i + 4 <= end; i += 4) {
        int s0 = g_csr[i], s1 = g_csr[i+1], s2 = g_csr[i+2], s3 = g_csr[i+3];
        float l0 = g_als[s0 * HEADS + hh];
        float l1 = g_als[s1 * HEADS + hh];
        float l2 = g_als[s2 * HEADS + hh];
        float l3 = g_als[s3 * HEADS + hh];
        uint4 v0 = zh4[(size_t)s0 * 32 + zo];
        uint4 v1 = zh4[(size_t)s1 * 32 + zo];
        uint4 v2 = zh4[(size_t)s2 * 32 + zo];
        uint4 v3 = zh4[(size_t)s3 * 32 + zo];
        float e0 = l0 + ald, e1 = l1 + ald, e2 = l2 + ald, e3 = l3 + ald;
        e0 = (e0 > 0.f) ? e0 : 0.2f * e0;
        e1 = (e1 > 0.f) ? e1 : 0.2f * e1;
        e2 = (e2 > 0.f) ? e2 : 0.2f * e2;
        e3 = (e3 > 0.f) ? e3 : 0.2f * e3;
        float w0 = __expf(e0), w1 = __expf(e1), w2 = __expf(e2), w3 = __expf(e3);
        dsum += (w0 + w1) + (w2 + w3);
        {
            const __half2* p = (const __half2*)&v0;
            float2 q0 = __half22float2(p[0]), q1 = __half22float2(p[1]);
            float2 q2 = __half22float2(p[2]), q3 = __half22float2(p[3]);
            a0 = fmaf(w0, q0.x, a0); a1 = fmaf(w0, q0.y, a1);
            a2 = fmaf(w0, q1.x, a2); a3 = fmaf(w0, q1.y, a3);
            a4 = fmaf(w0, q2.x, a4); a5 = fmaf(w0, q2.y, a5);
            a6 = fmaf(w0, q3.x, a6); a7 = fmaf(w0, q3.y, a7);
        }
        {
            const __half2* p = (const __half2*)&v1;
            float2 q0 = __half22float2(p[0]), q1 = __half22float2(p[1]);
            float2 q2 = __half22float2(p[2]), q3 = __half22float2(p[3]);
            a0 = fmaf(w1, q0.x, a0); a1 = fmaf(w1, q0.y, a1);
            a2 = fmaf(w1, q1.x, a2); a3 = fmaf(w1, q1.y, a3);
            a4 = fmaf(w1, q2.x, a4); a5 = fmaf(w1, q2.y, a5);
            a6 = fmaf(w1, q3.x, a6); a7 = fmaf(w1, q3.y, a7);
        }
        {
            const __half2* p = (const __half2*)&v2;
            float2 q0 = __half22float2(p[0]), q1 = __half22float2(p[1]);
            float2 q2 = __half22float2(p[2]), q3 = __half22float2(p[3]);
            a0 = fmaf(w2, q0.x, a0); a1 = fmaf(w2, q0.y, a1);
            a2 = fmaf(w2, q1.x, a2); a3 = fmaf(w2, q1.y, a3);
            a4 = fmaf(w2, q2.x, a4); a5 = fmaf(w2, q2.y, a5);
            a6 = fmaf(w2, q3.x, a6); a7 = fmaf(w2, q3.y, a7);
        }
        {
            const __half2* p = (const __half2*)&v3;
            float2 q0 = __half22float2(p[0]), q1 = __half22float2(p[1]);
            float2 q2 = __half22float2(p[2]), q3 = __half22float2(p[3]);
            a0 = fmaf(w3, q0.x, a0); a1 = fmaf(w3, q0.y, a1);
            a2 = fmaf(w3, q1.x, a2); a3 = fmaf(w3, q1.y, a3);
            a4 = fmaf(w3, q2.x, a4); a5 = fmaf(w3, q2.y, a5);
            a6 = fmaf(w3, q3.x, a6); a7 = fmaf(w3, q3.y, a7);
        }
    }
    for (; i < end; i++) {
        int s = g_csr[i];
        float e = g_als[s * HEADS + hh] + ald;
        e = (e > 0.f) ? e : 0.2f * e;
        float w = __expf(e);
        uint4 v = zh4[(size_t)s * 32 + zo];
        const __half2* p = (const __half2*)&v;
        float2 q0 = __half22float2(p[0]), q1 = __half22float2(p[1]);
        float2 q2 = __half22float2(p[2]), q3 = __half22float2(p[3]);
        dsum += w;
        a0 = fmaf(w, q0.x, a0); a1 = fmaf(w, q0.y, a1);
        a2 = fmaf(w, q1.x, a2); a3 = fmaf(w, q1.y, a3);
        a4 = fmaf(w, q2.x, a4); a5 = fmaf(w, q2.y, a5);
        a6 = fmaf(w, q3.x, a6); a7 = fmaf(w, q3.y, a7);
    }
    float inv = 1.f / (dsum + 1e-16f);
    a0*=inv; a1*=inv; a2*=inv; a3*=inv; a4*=inv; a5*=inv; a6*=inv; a7*=inv;

    #pragma unroll
    for (int m = 8; m <= 16; m <<= 1) {
        a0 += __shfl_xor_sync(0xffffffffu, a0, m);
        a1 += __shfl_xor_sync(0xffffffffu, a1, m);
        a2 += __shfl_xor_sync(0xffffffffu, a2, m);
        a3 += __shfl_xor_sync(0xffffffffu, a3, m);
        a4 += __shfl_xor_sync(0xffffffffu, a4, m);
        a5 += __shfl_xor_sync(0xffffffffu, a5, m);
        a6 += __shfl_xor_sync(0xffffffffu, a6, m);
        a7 += __shfl_xor_sync(0xffffffffu, a7, m);
    }
    if (hh == 0) {
        int fb = fg * 8;
        float* o = g_h + (size_t)(cur ^ 1) * NPAD * HID + (size_t)n * HID + fb;
        o[0] = fmaxf(0.25f * a0 + bg[fb + 0], 0.f);
        o[1] = fmaxf(0.25f * a1 + bg[fb + 1], 0.f);
        o[2] = fmaxf(0.25f * a2 + bg[fb + 2], 0.f);
        o[3] = fmaxf(0.25f * a3 + bg[fb + 3], 0.f);
        o[4] = fmaxf(0.25f * a4 + bg[fb + 4], 0.f);
        o[5] = fmaxf(0.25f * a5 + bg[fb + 5], 0.f);
        o[6] = fmaxf(0.25f * a6 + bg[fb + 6], 0.f);
        o[7] = fmaxf(0.25f * a7 + bg[fb + 7], 0.f);
    }
}

// ---------------- global mean pool --------------------------------------------
__global__ void k_pool(const int* __restrict__ batch, int cur) {
    __shared__ int s_lo, s_hi;
    __shared__ float red[256];
    int g = blockIdx.x;
    if (threadIdx.x == 0) {
        int lo = 0, hi = NNODES;
        while (lo < hi) { int m = (lo + hi) >> 1; if (batch[m] < g) lo = m + 1; else hi = m; }
        s_lo = lo;
        lo = 0; hi = NNODES;
        while (lo < hi) { int m = (lo + hi) >> 1; if (batch[m] < g + 1) lo = m + 1; else hi = m; }
        s_hi = lo;
    }
    __syncthreads();
    int lo = s_lo, hi = s_hi;
    int f = threadIdx.x & 63, r = threadIdx.x >> 6;
    const float* h = g_h + (size_t)cur * NPAD * HID;
    float acc = 0.f;
    for (int n = lo + r; n < hi; n += 4) acc += h[(size_t)n * HID + f];
    red[threadIdx.x] = acc;
    __syncthreads();
    if (threadIdx.x < 64) {
        float v = red[f] + red[64 + f] + red[128 + f] + red[192 + f];
        float cnt = (float)max(hi - lo, 1);
        g_hg[g * HID + f] = v / cnt;
    }
}

// ---------------- final FC (2 outputs per thread) ------------------------------
__global__ void __launch_bounds__(256) k_fc(const float* __restrict__ Wfc,
                                            const float* __restrict__ bfc,
                                            float* __restrict__ out) {
    __shared__ float hg[NG * HID];
    int t = threadIdx.x;
    for (int i = t; i < NG * HID; i += 256) hg[i] = g_hg[i];
    __syncthreads();
    int o2 = blockIdx.x * 256 + t;
    if (o2 >= OUTF / 2) return;
    const float2* W2 = (const float2*)Wfc;
    float2 b2 = ((const float2*)bfc)[o2];
    float acc0[NG], acc1[NG];
    #pragma unroll
    for (int g = 0; g < NG; g++) { acc0[g] = b2.x; acc1[g] = b2.y; }
    for (int f = 0; f < HID; f++) {
        float2 w = W2[(size_t)f * (OUTF / 2) + o2];
        #pragma unroll
        for (int g = 0; g < NG; g++) {
            float hv = hg[g * HID + f];
            acc0[g] = fmaf(hv, w.x, acc0[g]);
            acc1[g] = fmaf(hv, w.y, acc1[g]);
        }
    }
    float2* out2 = (float2*)out;
    #pragma unroll
    for (int g = 0; g < NG; g++)
        out2[(size_t)g * (OUTF / 2) + o2] = make_float2(acc0[g], acc1[g]);
}

// ---------------- launch --------------------------------------------------------
extern "C" void kernel_launch(void* const* d_in, const int* in_sizes, int n_in,
                              void* d_out, int out_size) {
    const float* x     = (const float*)d_in[0];
    const int*   ei    = (const int*)d_in[1];
    const int*   batch = (const int*)d_in[3];
    const float* W_emb = (const float*)d_in[4];
    const float* b_emb = (const float*)d_in[5];
    const float* W_gat = (const float*)d_in[6];
    const float* a_src = (const float*)d_in[7];
    const float* a_dst = (const float*)d_in[8];
    const float* b_gat = (const float*)d_in[9];
    const float* W_fc  = (const float*)d_in[10];
    const float* b_fc  = (const float*)d_in[11];
    float* out = (float*)d_out;

    void* degp = nullptr;
    cudaGetSymbolAddress(&degp, g_deg);
    cudaMemsetAsync(degp, 0, NNODES * sizeof(int));

    // kernel launch #4 = k_emb (ncu capture window)
    k_count<<<(NEDGES + 255) / 256, 256>>>(ei);
    k_bsum<<<NBLK, 256>>>();
    k_bscan<<<1, 256>>>();
    k_emb<<<NEBLK, 256>>>(x, W_emb, b_emb);
    k_offsets<<<NBLK, 256>>>();
    k_scatter<<<(NEDGES + 255) / 256, 256>>>(ei);
    k_z<<<NZBLK, 256>>>(W_gat, a_src, a_dst, 0);
    k_agg<<<(NNODES * 32 + 255) / 256, 256>>>(b_gat, 0);

    int cur = 1;
    for (int l = 1; l < 3; l++) {
        k_z<<<NZBLK, 256>>>(W_gat + (size_t)l * HID * ZW,
                            a_src + (size_t)l * HEADS * HID,
                            a_dst + (size_t)l * HEADS * HID, cur);
        k_agg<<<(NNODES * 32 + 255) / 256, 256>>>(b_gat + (size_t)l * HID, cur);
        cur ^= 1;
    }

    k_pool<<<NG, 256>>>(batch, cur);
    k_fc<<<(OUTF / 2 + 255) / 256, 256>>>(W_fc, b_fc, out);
}

// round 13
// speedup vs baseline: 3.1266x; 1.3247x over previous
#include <cuda_runtime.h>
#include <cuda_bf16.h>
#include <cuda_fp16.h>
#include <cstdint>
#include <math.h>

typedef unsigned long long ull;
typedef unsigned int u32;

#define NNODES 50000
#define NEDGES 500000
#define ETOT   (NEDGES + NNODES)
#define INF    128
#define HID    64
#define HEADS  4
#define ZW     (HEADS * HID)       // 256
#define NG     16
#define OUTF   326000
#define NPAD   50048               // multiple of 128
#define NEBLK  (NPAD / 128)        // 391 emb tiles
#define NZBLK  (NPAD / 64)         // 782 z tiles
#define NBLK   196                 // ceil(NNODES/256)

#define FMA2(d,a,b,c) asm("fma.rn.f32x2 %0, %1, %2, %3;" : "=l"(d) : "l"(a), "l"(b), "l"(c))
#define PK2(d,lo,hi)  asm("mov.b64 %0, {%1, %2};" : "=l"(d) : "f"(lo), "f"(hi))
#define UPK2(lo,hi,s) asm("mov.b64 {%0, %1}, %2;" : "=f"(lo), "=f"(hi) : "l"(s))

#define LDSM4(r0,r1,r2,r3,addr) \
    asm volatile("ldmatrix.sync.aligned.m8n8.x4.shared.b16 {%0,%1,%2,%3}, [%4];" \
        : "=r"(r0),"=r"(r1),"=r"(r2),"=r"(r3) : "r"(addr))
#define LDSM4T(r0,r1,r2,r3,addr) \
    asm volatile("ldmatrix.sync.aligned.m8n8.x4.trans.shared.b16 {%0,%1,%2,%3}, [%4];" \
        : "=r"(r0),"=r"(r1),"=r"(r2),"=r"(r3) : "r"(addr))
#define MMA16816(d,a0,a1,a2,a3,b0,b1) \
    asm volatile("mma.sync.aligned.m16n8k16.row.col.f32.f16.f16.f32 " \
        "{%0,%1,%2,%3},{%4,%5,%6,%7},{%8,%9},{%0,%1,%2,%3};" \
        : "+f"(d[0]),"+f"(d[1]),"+f"(d[2]),"+f"(d[3]) \
        : "r"(a0),"r"(a1),"r"(a2),"r"(a3),"r"(b0),"r"(b1))

// ---------------- scratch ----------------------------------------------------
__device__ float  g_h[(size_t)NPAD * HID];                 // fp32 h (pool input)
__device__ __align__(16) __half g_hh[(size_t)NPAD * HID];  // fp16 h (GEMM input)
__device__ __align__(16) __half g_wh[3 * HID * ZW];        // fp16 W_gat
__device__ __align__(16) __half g_zh[(size_t)NPAD * ZW];   // fp16 z
__device__ float  g_als[NPAD * HEADS];
__device__ float  g_ald[NPAD * HEADS];
__device__ int    g_deg[NNODES];
__device__ int    g_off[NNODES + 1];
__device__ int    g_cur[NNODES];
__device__ int    g_csr[ETOT];
__device__ int    g_bsum[256];
__device__ int    g_boff[256];
__device__ float  g_hg[NG * HID];

// ---------------- CSR build --------------------------------------------------
__global__ void k_count(const int* __restrict__ ei) {
    int e = blockIdx.x * blockDim.x + threadIdx.x;
    if (e >= NEDGES) return;
    atomicAdd(&g_deg[ei[NEDGES + e]], 1);
}

__global__ void k_bsum() {
    __shared__ int sm[256];
    int i = blockIdx.x * 256 + threadIdx.x;
    sm[threadIdx.x] = (i < NNODES) ? (g_deg[i] + 1) : 0;   // +1 self-loop
    __syncthreads();
    for (int o = 128; o; o >>= 1) {
        if (threadIdx.x < o) sm[threadIdx.x] += sm[threadIdx.x + o];
        __syncthreads();
    }
    if (threadIdx.x == 0) g_bsum[blockIdx.x] = sm[0];
}

__global__ void k_bscan() {
    __shared__ int sm[512];
    int t = threadIdx.x;
    sm[t] = 0;
    sm[256 + t] = (t < NBLK) ? g_bsum[t] : 0;
    __syncthreads();
    for (int d = 1; d < 256; d <<= 1) {
        int v = sm[256 + t - d];
        __syncthreads();
        sm[256 + t] += v;
        __syncthreads();
    }
    g_boff[t] = sm[255 + t];
    if (t == 0) g_off[NNODES] = ETOT;
}

__global__ void k_offsets() {
    __shared__ int sm[512];
    int t = threadIdx.x;
    int i = blockIdx.x * 256 + t;
    int d = (i < NNODES) ? (g_deg[i] + 1) : 0;
    sm[t] = 0;
    sm[256 + t] = d;
    __syncthreads();
    for (int dd = 1; dd < 256; dd <<= 1) {
        int v = sm[256 + t - dd];
        __syncthreads();
        sm[256 + t] += v;
        __syncthreads();
    }
    if (i < NNODES) {
        int run = g_boff[blockIdx.x] + sm[255 + t];
        g_off[i] = run;
        g_csr[run] = i;
        g_cur[i] = run + 1;
    }
}

__global__ void k_scatter(const int* __restrict__ ei) {
    int e = blockIdx.x * blockDim.x + threadIdx.x;
    if (e >= NEDGES) return;
    int s = ei[e];
    int p = atomicAdd(&g_cur[ei[NEDGES + e]], 1);
    g_csr[p] = s;
}

// ---------------- W_gat fp32 -> fp16 (all 3 layers, one shot) -----------------
__global__ void k_wcvt(const float* __restrict__ Wg) {
    int i = blockIdx.x * 256 + threadIdx.x;    // float4 index, 12288 total
    float4 v = ((const float4*)Wg)[i];
    __half2* dst = (__half2*)g_wh;
    dst[i * 2]     = __floats2half2_rn(v.x, v.y);
    dst[i * 2 + 1] = __floats2half2_rn(v.z, v.w);
}

// ---------------- embedding GEMM -> fp16 h ------------------------------------
__global__ void __launch_bounds__(256, 3) k_emb(const float* __restrict__ x,
                                                const float* __restrict__ W,
                                                const float* __restrict__ b) {
    __shared__ __align__(16) float xs[32 * 132];
    __shared__ float4 ws4[32 * 16];
    int tid = threadIdx.x;
    int n0 = blockIdx.x * 128;
    int ni = tid >> 5;
    int cj = tid & 31;
    int nsub = ni * 16 + (cj >> 3) * 4;
    int cb = (cj & 7) * 8;

    ull acc[8][2];
    #pragma unroll
    for (int c = 0; c < 8; c++) { acc[c][0] = 0ull; acc[c][1] = 0ull; }

    #pragma unroll
    for (int ch = 0; ch < 4; ch++) {
        int fb = ch * 32;
        __syncthreads();
        const float4* Wg4 = (const float4*)(W + fb * HID);
        ws4[tid] = Wg4[tid];
        ws4[tid + 256] = Wg4[tid + 256];
        #pragma unroll
        for (int j = 0; j < 4; j++) {
            int idx = tid + 256 * j;
            int nl = idx >> 3;
            int fq = idx & 7;
            int n = n0 + nl;
            float4 v = (n < NNODES) ? *(const float4*)&x[(size_t)n * INF + fb + fq * 4]
                                    : make_float4(0.f, 0.f, 0.f, 0.f);
            xs[(fq * 4 + 0) * 132 + nl] = v.x;
            xs[(fq * 4 + 1) * 132 + nl] = v.y;
            xs[(fq * 4 + 2) * 132 + nl] = v.z;
            xs[(fq * 4 + 3) * 132 + nl] = v.w;
        }
        __syncthreads();
        #pragma unroll 4
        for (int f = 0; f < 32; f++) {
            float4 hv = *(const float4*)&xs[f * 132 + nsub];
            float4 wa = ws4[f * 16 + (cj & 7) * 2];
            float4 wb = ws4[f * 16 + (cj & 7) * 2 + 1];
            ull hp0, hp1;
            PK2(hp0, hv.x, hv.y);
            PK2(hp1, hv.z, hv.w);
            float wv[8] = {wa.x, wa.y, wa.z, wa.w, wb.x, wb.y, wb.z, wb.w};
            #pragma unroll
            for (int c = 0; c < 8; c++) {
                ull wd; PK2(wd, wv[c], wv[c]);
                FMA2(acc[c][0], hp0, wd, acc[c][0]);
                FMA2(acc[c][1], hp1, wd, acc[c][1]);
            }
        }
    }

    float4 b0 = *(const float4*)&b[cb];
    float4 b1 = *(const float4*)&b[cb + 4];
    float bv[8] = {b0.x, b0.y, b0.z, b0.w, b1.x, b1.y, b1.z, b1.w};
    #pragma unroll
    for (int p = 0; p < 2; p++) {
        float lo[8], hi[8];
        #pragma unroll
        for (int c = 0; c < 8; c++) {
            UPK2(lo[c], hi[c], acc[c][p]);
            lo[c] += bv[c]; hi[c] += bv[c];
        }
        union { uint4 u; __half2 h[4]; } pl, ph;
        #pragma unroll
        for (int q = 0; q < 4; q++) {
            pl.h[q] = __floats2half2_rn(lo[2 * q], lo[2 * q + 1]);
            ph.h[q] = __floats2half2_rn(hi[2 * q], hi[2 * q + 1]);
        }
        *(uint4*)&g_hh[(size_t)(n0 + nsub + 2 * p) * HID + cb] = pl.u;
        *(uint4*)&g_hh[(size_t)(n0 + nsub + 2 * p + 1) * HID + cb] = ph.u;
    }
}

// ---------------- z GEMM via HMMA (64 nodes x 256 cols/block) + fused logits --
__global__ void __launch_bounds__(256, 2) k_z(int layer,
                                              const float* __restrict__ asrc,
                                              const float* __restrict__ adst) {
    __shared__ __align__(16) __half sA[64 * 72];    // h tile, padded rows
    __shared__ __align__(16) __half sB[64 * 264];   // W, padded rows
    const __half* Wh = g_wh + (size_t)layer * HID * ZW;
    int tid = threadIdx.x;
    int lane = tid & 31, warp = tid >> 5;
    int wm = warp >> 2, wn = warp & 3;
    int n0 = blockIdx.x * 64;

    // stage A: 64 rows x 64 halves (8 uint4/row)
    const uint4* hh4 = (const uint4*)(g_hh + (size_t)n0 * HID);
    #pragma unroll
    for (int j = 0; j < 2; j++) {
        int idx = tid + 256 * j;
        int row = idx >> 3, q = idx & 7;
        *(uint4*)&sA[row * 72 + q * 8] = hh4[row * 8 + q];
    }
    // stage B: 64 rows x 256 halves (32 uint4/row)
    const uint4* w4 = (const uint4*)Wh;
    #pragma unroll
    for (int j = 0; j < 8; j++) {
        int idx = tid + 256 * j;            // 0..2047
        int row = idx >> 5, q = idx & 31;   // 32 uint4 per row
        *(uint4*)&sB[row * 264 + q * 8] = w4[row * 32 + q];
    }
    __syncthreads();

    float acc[2][8][4];
    #pragma unroll
    for (int mt = 0; mt < 2; mt++)
        #pragma unroll
        for (int nt = 0; nt < 8; nt++)
            #pragma unroll
            for (int r = 0; r < 4; r++) acc[mt][nt][r] = 0.f;

    u32 sa = (u32)__cvta_generic_to_shared(sA);
    u32 sb = (u32)__cvta_generic_to_shared(sB);

    #pragma unroll
    for (int ks = 0; ks < 4; ks++) {
        u32 a[2][4];
        #pragma unroll
        for (int mt = 0; mt < 2; mt++) {
            u32 ad = sa + (u32)(((wm * 32 + mt * 16 + (lane & 15)) * 72
                                 + ks * 16 + (lane >> 4) * 8) << 1);
            LDSM4(a[mt][0], a[mt][1], a[mt][2], a[mt][3], ad);
        }
        #pragma unroll
        for (int nt2 = 0; nt2 < 4; nt2++) {
            u32 bd = sb + (u32)(((ks * 16 + (lane & 15)) * 264
                                 + wn * 64 + nt2 * 16 + (lane >> 4) * 8) << 1);
            u32 b0, b1, b2, b3;
            LDSM4T(b0, b1, b2, b3, bd);
            #pragma unroll
            for (int mt = 0; mt < 2; mt++) {
                MMA16816(acc[mt][nt2 * 2],     a[mt][0], a[mt][1], a[mt][2], a[mt][3], b0, b1);
                MMA16816(acc[mt][nt2 * 2 + 1], a[mt][0], a[mt][1], a[mt][2], a[mt][3], b2, b3);
            }
        }
    }

    // epilogue: store fp16 z + fused per-head attention logits (head == wn)
    float2 asv[8], adv[8];
    #pragma unroll
    for (int nt = 0; nt < 8; nt++) {
        int c = wn * 64 + nt * 8 + (lane & 3) * 2;
        asv[nt] = *(const float2*)&asrc[c];
        adv[nt] = *(const float2*)&adst[c];
    }
    #pragma unroll
    for (int mt = 0; mt < 2; mt++) {
        int r0 = n0 + wm * 32 + mt * 16 + (lane >> 2);
        float s0 = 0.f, s1 = 0.f, d0 = 0.f, d1 = 0.f;
        #pragma unroll
        for (int nt = 0; nt < 8; nt++) {
            s0 += acc[mt][nt][0] * asv[nt].x + acc[mt][nt][1] * asv[nt].y;
            s1 += acc[mt][nt][2] * asv[nt].x + acc[mt][nt][3] * asv[nt].y;
            d0 += acc[mt][nt][0] * adv[nt].x + acc[mt][nt][1] * adv[nt].y;
            d1 += acc[mt][nt][2] * adv[nt].x + acc[mt][nt][3] * adv[nt].y;
            int c = wn * 64 + nt * 8 + (lane & 3) * 2;
            *(__half2*)&g_zh[(size_t)r0 * ZW + c] =
                __floats2half2_rn(acc[mt][nt][0], acc[mt][nt][1]);
            *(__half2*)&g_zh[(size_t)(r0 + 8) * ZW + c] =
                __floats2half2_rn(acc[mt][nt][2], acc[mt][nt][3]);
        }
        #pragma unroll
        for (int o = 1; o <= 2; o <<= 1) {
            s0 += __shfl_xor_sync(0xffffffffu, s0, o);
            s1 += __shfl_xor_sync(0xffffffffu, s1, o);
            d0 += __shfl_xor_sync(0xffffffffu, d0, o);
            d1 += __shfl_xor_sync(0xffffffffu, d1, o);
        }
        if ((lane & 3) == 0) {
            g_als[r0 * HEADS + wn] = s0;
            g_als[(r0 + 8) * HEADS + wn] = s1;
            g_ald[r0 * HEADS + wn] = d0;
            g_ald[(r0 + 8) * HEADS + wn] = d1;
        }
    }
}

// ---------------- per-dst aggregation (warp/node, fp16 z, 4-way unroll) ------
__global__ void __launch_bounds__(256) k_agg(const float* __restrict__ bg) {
    int wid = (blockIdx.x * blockDim.x + threadIdx.x) >> 5;
    if (wid >= NNODES) return;
    int n = wid;
    int lane = threadIdx.x & 31;
    int hh = lane >> 3;
    int fg = lane & 7;

    float ald = g_ald[n * HEADS + hh];
    float a0=0,a1=0,a2=0,a3=0,a4=0,a5=0,a6=0,a7=0;
    float dsum = 0.f;

    const uint4* zh4 = (const uint4*)g_zh;
    int zo = hh * 8 + fg;
    int beg = g_off[n], end = g_off[n + 1];
    int i = beg;
    for (; i + 4 <= end; i += 4) {
        int s0 = g_csr[i], s1 = g_csr[i+1], s2 = g_csr[i+2], s3 = g_csr[i+3];
        float l0 = g_als[s0 * HEADS + hh];
        float l1 = g_als[s1 * HEADS + hh];
        float l2 = g_als[s2 * HEADS + hh];
        float l3 = g_als[s3 * HEADS + hh];
        uint4 v0 = zh4[(size_t)s0 * 32 + zo];
        uint4 v1 = zh4[(size_t)s1 * 32 + zo];
        uint4 v2 = zh4[(size_t)s2 * 32 + zo];
        uint4 v3 = zh4[(size_t)s3 * 32 + zo];
        float e0 = l0 + ald, e1 = l1 + ald, e2 = l2 + ald, e3 = l3 + ald;
        e0 = (e0 > 0.f) ? e0 : 0.2f * e0;
        e1 = (e1 > 0.f) ? e1 : 0.2f * e1;
        e2 = (e2 > 0.f) ? e2 : 0.2f * e2;
        e3 = (e3 > 0.f) ? e3 : 0.2f * e3;
        float w0 = __expf(e0), w1 = __expf(e1), w2 = __expf(e2), w3 = __expf(e3);
        dsum += (w0 + w1) + (w2 + w3);
        {
            const __half2* p = (const __half2*)&v0;
            float2 q0 = __half22float2(p[0]), q1 = __half22float2(p[1]);
            float2 q2 = __half22float2(p[2]), q3 = __half22float2(p[3]);
            a0 = fmaf(w0, q0.x, a0); a1 = fmaf(w0, q0.y, a1);
            a2 = fmaf(w0, q1.x, a2); a3 = fmaf(w0, q1.y, a3);
            a4 = fmaf(w0, q2.x, a4); a5 = fmaf(w0, q2.y, a5);
            a6 = fmaf(w0, q3.x, a6); a7 = fmaf(w0, q3.y, a7);
        }
        {
            const __half2* p = (const __half2*)&v1;
            float2 q0 = __half22float2(p[0]), q1 = __half22float2(p[1]);
            float2 q2 = __half22float2(p[2]), q3 = __half22float2(p[3]);
            a0 = fmaf(w1, q0.x, a0); a1 = fmaf(w1, q0.y, a1);
            a2 = fmaf(w1, q1.x, a2); a3 = fmaf(w1, q1.y, a3);
            a4 = fmaf(w1, q2.x, a4); a5 = fmaf(w1, q2.y, a5);
            a6 = fmaf(w1, q3.x, a6); a7 = fmaf(w1, q3.y, a7);
        }
        {
            const __half2* p = (const __half2*)&v2;
            float2 q0 = __half22float2(p[0]), q1 = __half22float2(p[1]);
            float2 q2 = __half22float2(p[2]), q3 = __half22float2(p[3]);
            a0 = fmaf(w2, q0.x, a0); a1 = fmaf(w2, q0.y, a1);
            a2 = fmaf(w2, q1.x, a2); a3 = fmaf(w2, q1.y, a3);
            a4 = fmaf(w2, q2.x, a4); a5 = fmaf(w2, q2.y, a5);
            a6 = fmaf(w2, q3.x, a6); a7 = fmaf(w2, q3.y, a7);
        }
        {
            const __half2* p = (const __half2*)&v3;
            float2 q0 = __half22float2(p[0]), q1 = __half22float2(p[1]);
            float2 q2 = __half22float2(p[2]), q3 = __half22float2(p[3]);
            a0 = fmaf(w3, q0.x, a0); a1 = fmaf(w3, q0.y, a1);
            a2 = fmaf(w3, q1.x, a2); a3 = fmaf(w3, q1.y, a3);
            a4 = fmaf(w3, q2.x, a4); a5 = fmaf(w3, q2.y, a5);
            a6 = fmaf(w3, q3.x, a6); a7 = fmaf(w3, q3.y, a7);
        }
    }
    for (; i < end; i++) {
        int s = g_csr[i];
        float e = g_als[s * HEADS + hh] + ald;
        e = (e > 0.f) ? e : 0.2f * e;
        float w = __expf(e);
        uint4 v = zh4[(size_t)s * 32 + zo];
        const __half2* p = (const __half2*)&v;
        float2 q0 = __half22float2(p[0]), q1 = __half22float2(p[1]);
        float2 q2 = __half22float2(p[2]), q3 = __half22float2(p[3]);
        dsum += w;
        a0 = fmaf(w, q0.x, a0); a1 = fmaf(w, q0.y, a1);
        a2 = fmaf(w, q1.x, a2); a3 = fmaf(w, q1.y, a3);
        a4 = fmaf(w, q2.x, a4); a5 = fmaf(w, q2.y, a5);
        a6 = fmaf(w, q3.x, a6); a7 = fmaf(w, q3.y, a7);
    }
    float inv = 1.f / (dsum + 1e-16f);
    a0*=inv; a1*=inv; a2*=inv; a3*=inv; a4*=inv; a5*=inv; a6*=inv; a7*=inv;

    #pragma unroll
    for (int m = 8; m <= 16; m <<= 1) {
        a0 += __shfl_xor_sync(0xffffffffu, a0, m);
        a1 += __shfl_xor_sync(0xffffffffu, a1, m);
        a2 += __shfl_xor_sync(0xffffffffu, a2, m);
        a3 += __shfl_xor_sync(0xffffffffu, a3, m);
        a4 += __shfl_xor_sync(0xffffffffu, a4, m);
        a5 += __shfl_xor_sync(0xffffffffu, a5, m);
        a6 += __shfl_xor_sync(0xffffffffu, a6, m);
        a7 += __shfl_xor_sync(0xffffffffu, a7, m);
    }
    if (hh == 0) {
        int fb = fg * 8;
        float r0 = fmaxf(0.25f * a0 + bg[fb + 0], 0.f);
        float r1 = fmaxf(0.25f * a1 + bg[fb + 1], 0.f);
        float r2 = fmaxf(0.25f * a2 + bg[fb + 2], 0.f);
        float r3 = fmaxf(0.25f * a3 + bg[fb + 3], 0.f);
        float r4 = fmaxf(0.25f * a4 + bg[fb + 4], 0.f);
        float r5 = fmaxf(0.25f * a5 + bg[fb + 5], 0.f);
        float r6 = fmaxf(0.25f * a6 + bg[fb + 6], 0.f);
        float r7 = fmaxf(0.25f * a7 + bg[fb + 7], 0.f);
        float* o = g_h + (size_t)n * HID + fb;
        ((float4*)o)[0] = make_float4(r0, r1, r2, r3);
        ((float4*)o)[1] = make_float4(r4, r5, r6, r7);
        union { uint4 u; __half2 h[4]; } pk;
        pk.h[0] = __floats2half2_rn(r0, r1);
        pk.h[1] = __floats2half2_rn(r2, r3);
        pk.h[2] = __floats2half2_rn(r4, r5);
        pk.h[3] = __floats2half2_rn(r6, r7);
        *(uint4*)&g_hh[(size_t)n * HID + fb] = pk.u;
    }
}

// ---------------- global mean pool --------------------------------------------
__global__ void k_pool(const int* __restrict__ batch) {
    __shared__ int s_lo, s_hi;
    __shared__ float red[256];
    int g = blockIdx.x;
    if (threadIdx.x == 0) {
        int lo = 0, hi = NNODES;
        while (lo < hi) { int m = (lo + hi) >> 1; if (batch[m] < g) lo = m + 1; else hi = m; }
        s_lo = lo;
        lo = 0; hi = NNODES;
        while (lo < hi) { int m = (lo + hi) >> 1; if (batch[m] < g + 1) lo = m + 1; else hi = m; }
        s_hi = lo;
    }
    __syncthreads();
    int lo = s_lo, hi = s_hi;
    int f = threadIdx.x & 63, r = threadIdx.x >> 6;
    float acc = 0.f;
    for (int n = lo + r; n < hi; n += 4) acc += g_h[(size_t)n * HID + f];
    red[threadIdx.x] = acc;
    __syncthreads();
    if (threadIdx.x < 64) {
        float v = red[f] + red[64 + f] + red[128 + f] + red[192 + f];
        float cnt = (float)max(hi - lo, 1);
        g_hg[g * HID + f] = v / cnt;
    }
}

// ---------------- final FC (2 outputs per thread) ------------------------------
__global__ void __launch_bounds__(256) k_fc(const float* __restrict__ Wfc,
                                            const float* __restrict__ bfc,
                                            float* __restrict__ out) {
    __shared__ float hg[NG * HID];
    int t = threadIdx.x;
    for (int i = t; i < NG * HID; i += 256) hg[i] = g_hg[i];
    __syncthreads();
    int o2 = blockIdx.x * 256 + t;
    if (o2 >= OUTF / 2) return;
    const float2* W2 = (const float2*)Wfc;
    float2 b2 = ((const float2*)bfc)[o2];
    float acc0[NG], acc1[NG];
    #pragma unroll
    for (int g = 0; g < NG; g++) { acc0[g] = b2.x; acc1[g] = b2.y; }
    for (int f = 0; f < HID; f++) {
        float2 w = W2[(size_t)f * (OUTF / 2) + o2];
        #pragma unroll
        for (int g = 0; g < NG; g++) {
            float hv = hg[g * HID + f];
            acc0[g] = fmaf(hv, w.x, acc0[g]);
            acc1[g] = fmaf(hv, w.y, acc1[g]);
        }
    }
    float2* out2 = (float2*)out;
    #pragma unroll
    for (int g = 0; g < NG; g++)
        out2[(size_t)g * (OUTF / 2) + o2] = make_float2(acc0[g], acc1[g]);
}

// ---------------- launch --------------------------------------------------------
extern "C" void kernel_launch(void* const* d_in, const int* in_sizes, int n_in,
                              void* d_out, int out_size) {
    const float* x     = (const float*)d_in[0];
    const int*   ei    = (const int*)d_in[1];
    const int*   batch = (const int*)d_in[3];
    const float* W_emb = (const float*)d_in[4];
    const float* b_emb = (const float*)d_in[5];
    const float* W_gat = (const float*)d_in[6];
    const float* a_src = (const float*)d_in[7];
    const float* a_dst = (const float*)d_in[8];
    const float* b_gat = (const float*)d_in[9];
    const float* W_fc  = (const float*)d_in[10];
    const float* b_fc  = (const float*)d_in[11];
    float* out = (float*)d_out;

    void* degp = nullptr;
    cudaGetSymbolAddress(&degp, g_deg);
    cudaMemsetAsync(degp, 0, NNODES * sizeof(int));

    // kernel launch #4 = k_z (ncu capture window)
    k_count<<<(NEDGES + 255) / 256, 256>>>(ei);
    k_wcvt<<<48, 256>>>(W_gat);
    k_emb<<<NEBLK, 256>>>(x, W_emb, b_emb);
    k_z<<<NZBLK, 256>>>(0, a_src, a_dst);
    k_bsum<<<NBLK, 256>>>();
    k_bscan<<<1, 256>>>();
    k_offsets<<<NBLK, 256>>>();
    k_scatter<<<(NEDGES + 255) / 256, 256>>>(ei);
    k_agg<<<(NNODES * 32 + 255) / 256, 256>>>(b_gat);

    for (int l = 1; l < 3; l++) {
        k_z<<<NZBLK, 256>>>(l,
                            a_src + (size_t)l * HEADS * HID,
                            a_dst + (size_t)l * HEADS * HID);
        k_agg<<<(NNODES * 32 + 255) / 256, 256>>>(b_gat + (size_t)l * HID);
    }

    k_pool<<<NG, 256>>>(batch);
    k_fc<<<(OUTF / 2 + 255) / 256, 256>>>(W_fc, b_fc, out);
}

// round 14
// speedup vs baseline: 3.2889x; 1.0519x over previous
#include <cuda_runtime.h>
#include <cuda_bf16.h>
#include <cuda_fp16.h>
#include <cstdint>
#include <math.h>

typedef unsigned long long ull;
typedef unsigned int u32;

#define NNODES 50000
#define NEDGES 500000
#define ETOT   (NEDGES + NNODES)
#define INF    128
#define HID    64
#define HEADS  4
#define ZW     (HEADS * HID)       // 256
#define NG     16
#define OUTF   326000
#define NPAD   50048               // multiple of 128
#define NZBLK  (NPAD / 64)         // 782 z tiles
#define NBLK   196                 // ceil(NNODES/256)

#define LDSM4(r0,r1,r2,r3,addr) \
    asm volatile("ldmatrix.sync.aligned.m8n8.x4.shared.b16 {%0,%1,%2,%3}, [%4];" \
        : "=r"(r0),"=r"(r1),"=r"(r2),"=r"(r3) : "r"(addr))
#define LDSM4T(r0,r1,r2,r3,addr) \
    asm volatile("ldmatrix.sync.aligned.m8n8.x4.trans.shared.b16 {%0,%1,%2,%3}, [%4];" \
        : "=r"(r0),"=r"(r1),"=r"(r2),"=r"(r3) : "r"(addr))
#define MMA16816(d,a0,a1,a2,a3,b0,b1) \
    asm volatile("mma.sync.aligned.m16n8k16.row.col.f32.f16.f16.f32 " \
        "{%0,%1,%2,%3},{%4,%5,%6,%7},{%8,%9},{%0,%1,%2,%3};" \
        : "+f"(d[0]),"+f"(d[1]),"+f"(d[2]),"+f"(d[3]) \
        : "r"(a0),"r"(a1),"r"(a2),"r"(a3),"r"(b0),"r"(b1))

// ---------------- scratch ----------------------------------------------------
__device__ float  g_h[(size_t)NPAD * HID];                 // fp32 h (pool input)
__device__ __align__(16) __half g_hh[(size_t)NPAD * HID];  // fp16 h (GEMM input)
__device__ __align__(16) __half g_xh[(size_t)NPAD * INF];  // fp16 x
__device__ __align__(16) __half g_wh[3 * HID * ZW];        // fp16 W_gat
__device__ __align__(16) __half g_wf[INF * ZW];            // fp16 fused W_emb@W_gat0
__device__ float  g_bz[ZW];                                // fused bias row
__device__ __align__(16) __half g_zh[(size_t)NPAD * ZW];   // fp16 z
__device__ float  g_als[NPAD * HEADS];
__device__ float  g_ald[NPAD * HEADS];
__device__ int    g_deg[NNODES];
__device__ int    g_off[NNODES + 1];
__device__ int    g_cur[NNODES];
__device__ int    g_csr[ETOT];
__device__ int    g_bsum[256];
__device__ int    g_boff[256];
__device__ float  g_hg[NG * HID];

// ---------------- CSR build --------------------------------------------------
__global__ void k_count(const int* __restrict__ ei) {
    int e = blockIdx.x * blockDim.x + threadIdx.x;
    if (e >= NEDGES) return;
    atomicAdd(&g_deg[ei[NEDGES + e]], 1);
}

__global__ void k_bsum() {
    __shared__ int sm[256];
    int i = blockIdx.x * 256 + threadIdx.x;
    sm[threadIdx.x] = (i < NNODES) ? (g_deg[i] + 1) : 0;   // +1 self-loop
    __syncthreads();
    for (int o = 128; o; o >>= 1) {
        if (threadIdx.x < o) sm[threadIdx.x] += sm[threadIdx.x + o];
        __syncthreads();
    }
    if (threadIdx.x == 0) g_bsum[blockIdx.x] = sm[0];
}

__global__ void k_bscan() {
    __shared__ int sm[512];
    int t = threadIdx.x;
    sm[t] = 0;
    sm[256 + t] = (t < NBLK) ? g_bsum[t] : 0;
    __syncthreads();
    for (int d = 1; d < 256; d <<= 1) {
        int v = sm[256 + t - d];
        __syncthreads();
        sm[256 + t] += v;
        __syncthreads();
    }
    g_boff[t] = sm[255 + t];
    if (t == 0) g_off[NNODES] = ETOT;
}

__global__ void k_offsets() {
    __shared__ int sm[512];
    int t = threadIdx.x;
    int i = blockIdx.x * 256 + t;
    int d = (i < NNODES) ? (g_deg[i] + 1) : 0;
    sm[t] = 0;
    sm[256 + t] = d;
    __syncthreads();
    for (int dd = 1; dd < 256; dd <<= 1) {
        int v = sm[256 + t - dd];
        __syncthreads();
        sm[256 + t] += v;
        __syncthreads();
    }
    if (i < NNODES) {
        int run = g_boff[blockIdx.x] + sm[255 + t];
        g_off[i] = run;
        g_csr[run] = i;
        g_cur[i] = run + 1;
    }
}

__global__ void k_scatter(const int* __restrict__ ei) {
    int e = blockIdx.x * blockDim.x + threadIdx.x;
    if (e >= NEDGES) return;
    int s = ei[e];
    int p = atomicAdd(&g_cur[ei[NEDGES + e]], 1);
    g_csr[p] = s;
}

// ---------------- x fp32 -> fp16 (padded rows zeroed) -------------------------
__global__ void k_xcvt(const float* __restrict__ x) {
    int i = blockIdx.x * 256 + threadIdx.x;    // 800768 units of 8 halves
    int n = i >> 4;
    int off = (i & 15) * 8;
    union { uint4 u; __half2 h[4]; } pk;
    if (n < NNODES) {
        float4 v0 = *(const float4*)&x[(size_t)n * INF + off];
        float4 v1 = *(const float4*)&x[(size_t)n * INF + off + 4];
        pk.h[0] = __floats2half2_rn(v0.x, v0.y);
        pk.h[1] = __floats2half2_rn(v0.z, v0.w);
        pk.h[2] = __floats2half2_rn(v1.x, v1.y);
        pk.h[3] = __floats2half2_rn(v1.z, v1.w);
    } else {
        pk.u = make_uint4(0, 0, 0, 0);
    }
    *(uint4*)&g_xh[(size_t)n * INF + off] = pk.u;
}

// ---------------- W_gat fp32 -> fp16 (all 3 layers) ---------------------------
__global__ void k_wcvt(const float* __restrict__ Wg) {
    int i = blockIdx.x * 256 + threadIdx.x;    // float4 index, 12288 total
    float4 v = ((const float4*)Wg)[i];
    __half2* dst = (__half2*)g_wh;
    dst[i * 2]     = __floats2half2_rn(v.x, v.y);
    dst[i * 2 + 1] = __floats2half2_rn(v.z, v.w);
}

// ---------------- fused weights: Wf = W_emb @ W_gat0, bz = b_emb @ W_gat0 -----
__global__ void k_wfuse(const float* __restrict__ Wemb,
                        const float* __restrict__ bemb,
                        const float* __restrict__ Wg0) {
    __shared__ float we[HID];
    int r = blockIdx.x;                        // 0..127 rows, 128 = bias row
    int c = threadIdx.x;                       // 0..255
    if (r < INF) {
        if (c < HID) we[c] = Wemb[r * HID + c];
        __syncthreads();
        float acc = 0.f;
        #pragma unroll 8
        for (int k = 0; k < HID; k++) acc = fmaf(we[k], Wg0[k * ZW + c], acc);
        g_wf[r * ZW + c] = __float2half_rn(acc);
    } else {
        if (c < HID) we[c] = bemb[c];
        __syncthreads();
        float acc = 0.f;
        #pragma unroll 8
        for (int k = 0; k < HID; k++) acc = fmaf(we[k], Wg0[k * ZW + c], acc);
        g_bz[c] = acc;
    }
}

// ---------------- z GEMM via HMMA + fused logits ------------------------------
// layer 0: A = g_xh (K=128, 2 chunks), B = g_wf, bias g_bz
// layer 1,2: A = g_hh (K=64), B = g_wh + layer*HID*ZW
__global__ void __launch_bounds__(256, 2) k_z(int layer,
                                              const float* __restrict__ asrc,
                                              const float* __restrict__ adst) {
    __shared__ __align__(16) __half sA[64 * 72];    // A chunk (64n x 64k)
    __shared__ __align__(16) __half sB[64 * 264];   // B chunk (64k x 256c)
    const __half* A;
    const __half* B;
    int astride, kch;
    if (layer == 0) { A = g_xh; B = g_wf; astride = INF; kch = 2; }
    else { A = g_hh; B = g_wh + (size_t)layer * HID * ZW; astride = HID; kch = 1; }

    int tid = threadIdx.x;
    int lane = tid & 31, warp = tid >> 5;
    int wm = warp >> 2, wn = warp & 3;
    int n0 = blockIdx.x * 64;
    int rstride4 = astride >> 3;               // uint4 per A row

    float acc[2][8][4];
    #pragma unroll
    for (int mt = 0; mt < 2; mt++)
        #pragma unroll
        for (int nt = 0; nt < 8; nt++)
            #pragma unroll
            for (int r = 0; r < 4; r++) acc[mt][nt][r] = 0.f;

    u32 sa = (u32)__cvta_generic_to_shared(sA);
    u32 sb = (u32)__cvta_generic_to_shared(sB);
    const uint4* a4 = (const uint4*)(A + (size_t)n0 * astride);
    const uint4* w4 = (const uint4*)B;

    for (int ch = 0; ch < kch; ch++) {
        if (ch) __syncthreads();
        // stage A chunk: 64 rows x 64 halves (8 uint4/row)
        #pragma unroll
        for (int j = 0; j < 2; j++) {
            int idx = tid + 256 * j;
            int row = idx >> 3, q = idx & 7;
            *(uint4*)&sA[row * 72 + q * 8] = a4[row * rstride4 + ch * 8 + q];
        }
        // stage B chunk: 64 k-rows x 256 halves (32 uint4/row)
        #pragma unroll
        for (int j = 0; j < 8; j++) {
            int idx = tid + 256 * j;
            int row = idx >> 5, q = idx & 31;
            *(uint4*)&sB[row * 264 + q * 8] = w4[(ch * 64 + row) * 32 + q];
        }
        __syncthreads();

        #pragma unroll
        for (int ks = 0; ks < 4; ks++) {
            u32 a[2][4];
            #pragma unroll
            for (int mt = 0; mt < 2; mt++) {
                u32 ad = sa + (u32)(((wm * 32 + mt * 16 + (lane & 15)) * 72
                                     + ks * 16 + (lane >> 4) * 8) << 1);
                LDSM4(a[mt][0], a[mt][1], a[mt][2], a[mt][3], ad);
            }
            #pragma unroll
            for (int nt2 = 0; nt2 < 4; nt2++) {
                u32 bd = sb + (u32)(((ks * 16 + (lane & 15)) * 264
                                     + wn * 64 + nt2 * 16 + (lane >> 4) * 8) << 1);
                u32 b0, b1, b2, b3;
                LDSM4T(b0, b1, b2, b3, bd);
                #pragma unroll
                for (int mt = 0; mt < 2; mt++) {
                    MMA16816(acc[mt][nt2 * 2],     a[mt][0], a[mt][1], a[mt][2], a[mt][3], b0, b1);
                    MMA16816(acc[mt][nt2 * 2 + 1], a[mt][0], a[mt][1], a[mt][2], a[mt][3], b2, b3);
                }
            }
        }
    }

    // fused bias (layer 0 only): bias per column
    if (layer == 0) {
        #pragma unroll
        for (int nt = 0; nt < 8; nt++) {
            float2 b2 = ((const float2*)g_bz)[(wn * 64 + nt * 8) / 2 + (lane & 3)];
            #pragma unroll
            for (int mt = 0; mt < 2; mt++) {
                acc[mt][nt][0] += b2.x; acc[mt][nt][1] += b2.y;
                acc[mt][nt][2] += b2.x; acc[mt][nt][3] += b2.y;
            }
        }
    }

    // epilogue: store fp16 z + fused per-head attention logits (head == wn)
    float2 asv[8], adv[8];
    #pragma unroll
    for (int nt = 0; nt < 8; nt++) {
        int c = wn * 64 + nt * 8 + (lane & 3) * 2;
        asv[nt] = *(const float2*)&asrc[c];
        adv[nt] = *(const float2*)&adst[c];
    }
    #pragma unroll
    for (int mt = 0; mt < 2; mt++) {
        int r0 = n0 + wm * 32 + mt * 16 + (lane >> 2);
        float s0 = 0.f, s1 = 0.f, d0 = 0.f, d1 = 0.f;
        #pragma unroll
        for (int nt = 0; nt < 8; nt++) {
            s0 += acc[mt][nt][0] * asv[nt].x + acc[mt][nt][1] * asv[nt].y;
            s1 += acc[mt][nt][2] * asv[nt].x + acc[mt][nt][3] * asv[nt].y;
            d0 += acc[mt][nt][0] * adv[nt].x + acc[mt][nt][1] * adv[nt].y;
            d1 += acc[mt][nt][2] * adv[nt].x + acc[mt][nt][3] * adv[nt].y;
            int c = wn * 64 + nt * 8 + (lane & 3) * 2;
            *(__half2*)&g_zh[(size_t)r0 * ZW + c] =
                __floats2half2_rn(acc[mt][nt][0], acc[mt][nt][1]);
            *(__half2*)&g_zh[(size_t)(r0 + 8) * ZW + c] =
                __floats2half2_rn(acc[mt][nt][2], acc[mt][nt][3]);
        }
        #pragma unroll
        for (int o = 1; o <= 2; o <<= 1) {
            s0 += __shfl_xor_sync(0xffffffffu, s0, o);
            s1 += __shfl_xor_sync(0xffffffffu, s1, o);
            d0 += __shfl_xor_sync(0xffffffffu, d0, o);
            d1 += __shfl_xor_sync(0xffffffffu, d1, o);
        }
        if ((lane & 3) == 0) {
            g_als[r0 * HEADS + wn] = s0;
            g_als[(r0 + 8) * HEADS + wn] = s1;
            g_ald[r0 * HEADS + wn] = d0;
            g_ald[(r0 + 8) * HEADS + wn] = d1;
        }
    }
}

// ---------------- per-dst aggregation (warp/node, fp16 z, 4-way unroll) ------
__global__ void __launch_bounds__(256) k_agg(const float* __restrict__ bg) {
    int wid = (blockIdx.x * blockDim.x + threadIdx.x) >> 5;
    if (wid >= NNODES) return;
    int n = wid;
    int lane = threadIdx.x & 31;
    int hh = lane >> 3;
    int fg = lane & 7;

    float ald = g_ald[n * HEADS + hh];
    float a0=0,a1=0,a2=0,a3=0,a4=0,a5=0,a6=0,a7=0;
    float dsum = 0.f;

    const uint4* zh4 = (const uint4*)g_zh;
    int zo = hh * 8 + fg;
    int beg = g_off[n], end = g_off[n + 1];
    int i = beg;
    for (; i + 4 <= end; i += 4) {
        int s0 = g_csr[i], s1 = g_csr[i+1], s2 = g_csr[i+2], s3 = g_csr[i+3];
        float l0 = g_als[s0 * HEADS + hh];
        float l1 = g_als[s1 * HEADS + hh];
        float l2 = g_als[s2 * HEADS + hh];
        float l3 = g_als[s3 * HEADS + hh];
        uint4 v0 = zh4[(size_t)s0 * 32 + zo];
        uint4 v1 = zh4[(size_t)s1 * 32 + zo];
        uint4 v2 = zh4[(size_t)s2 * 32 + zo];
        uint4 v3 = zh4[(size_t)s3 * 32 + zo];
        float e0 = l0 + ald, e1 = l1 + ald, e2 = l2 + ald, e3 = l3 + ald;
        e0 = (e0 > 0.f) ? e0 : 0.2f * e0;
        e1 = (e1 > 0.f) ? e1 : 0.2f * e1;
        e2 = (e2 > 0.f) ? e2 : 0.2f * e2;
        e3 = (e3 > 0.f) ? e3 : 0.2f * e3;
        float w0 = __expf(e0), w1 = __expf(e1), w2 = __expf(e2), w3 = __expf(e3);
        dsum += (w0 + w1) + (w2 + w3);
        {
            const __half2* p = (const __half2*)&v0;
            float2 q0 = __half22float2(p[0]), q1 = __half22float2(p[1]);
            float2 q2 = __half22float2(p[2]), q3 = __half22float2(p[3]);
            a0 = fmaf(w0, q0.x, a0); a1 = fmaf(w0, q0.y, a1);
            a2 = fmaf(w0, q1.x, a2); a3 = fmaf(w0, q1.y, a3);
            a4 = fmaf(w0, q2.x, a4); a5 = fmaf(w0, q2.y, a5);
            a6 = fmaf(w0, q3.x, a6); a7 = fmaf(w0, q3.y, a7);
        }
        {
            const __half2* p = (const __half2*)&v1;
            float2 q0 = __half22float2(p[0]), q1 = __half22float2(p[1]);
            float2 q2 = __half22float2(p[2]), q3 = __half22float2(p[3]);
            a0 = fmaf(w1, q0.x, a0); a1 = fmaf(w1, q0.y, a1);
            a2 = fmaf(w1, q1.x, a2); a3 = fmaf(w1, q1.y, a3);
            a4 = fmaf(w1, q2.x, a4); a5 = fmaf(w1, q2.y, a5);
            a6 = fmaf(w1, q3.x, a6); a7 = fmaf(w1, q3.y, a7);
        }
        {
            const __half2* p = (const __half2*)&v2;
            float2 q0 = __half22float2(p[0]), q1 = __half22float2(p[1]);
            float2 q2 = __half22float2(p[2]), q3 = __half22float2(p[3]);
            a0 = fmaf(w2, q0.x, a0); a1 = fmaf(w2, q0.y, a1);
            a2 = fmaf(w2, q1.x, a2); a3 = fmaf(w2, q1.y, a3);
            a4 = fmaf(w2, q2.x, a4); a5 = fmaf(w2, q2.y, a5);
            a6 = fmaf(w2, q3.x, a6); a7 = fmaf(w2, q3.y, a7);
        }
        {
            const __half2* p = (const __half2*)&v3;
            float2 q0 = __half22float2(p[0]), q1 = __half22float2(p[1]);
            float2 q2 = __half22float2(p[2]), q3 = __half22float2(p[3]);
            a0 = fmaf(w3, q0.x, a0); a1 = fmaf(w3, q0.y, a1);
            a2 = fmaf(w3, q1.x, a2); a3 = fmaf(w3, q1.y, a3);
            a4 = fmaf(w3, q2.x, a4); a5 = fmaf(w3, q2.y, a5);
            a6 = fmaf(w3, q3.x, a6); a7 = fmaf(w3, q3.y, a7);
        }
    }
    for (; i < end; i++) {
        int s = g_csr[i];
        float e = g_als[s * HEADS + hh] + ald;
        e = (e > 0.f) ? e : 0.2f * e;
        float w = __expf(e);
        uint4 v = zh4[(size_t)s * 32 + zo];
        const __half2* p = (const __half2*)&v;
        float2 q0 = __half22float2(p[0]), q1 = __half22float2(p[1]);
        float2 q2 = __half22float2(p[2]), q3 = __half22float2(p[3]);
        dsum += w;
        a0 = fmaf(w, q0.x, a0); a1 = fmaf(w, q0.y, a1);
        a2 = fmaf(w, q1.x, a2); a3 = fmaf(w, q1.y, a3);
        a4 = fmaf(w, q2.x, a4); a5 = fmaf(w, q2.y, a5);
        a6 = fmaf(w, q3.x, a6); a7 = fmaf(w, q3.y, a7);
    }
    float inv = 1.f / (dsum + 1e-16f);
    a0*=inv; a1*=inv; a2*=inv; a3*=inv; a4*=inv; a5*=inv; a6*=inv; a7*=inv;

    #pragma unroll
    for (int m = 8; m <= 16; m <<= 1) {
        a0 += __shfl_xor_sync(0xffffffffu, a0, m);
        a1 += __shfl_xor_sync(0xffffffffu, a1, m);
        a2 += __shfl_xor_sync(0xffffffffu, a2, m);
        a3 += __shfl_xor_sync(0xffffffffu, a3, m);
        a4 += __shfl_xor_sync(0xffffffffu, a4, m);
        a5 += __shfl_xor_sync(0xffffffffu, a5, m);
        a6 += __shfl_xor_sync(0xffffffffu, a6, m);
        a7 += __shfl_xor_sync(0xffffffffu, a7, m);
    }
    if (hh == 0) {
        int fb = fg * 8;
        float r0 = fmaxf(0.25f * a0 + bg[fb + 0], 0.f);
        float r1 = fmaxf(0.25f * a1 + bg[fb + 1], 0.f);
        float r2 = fmaxf(0.25f * a2 + bg[fb + 2], 0.f);
        float r3 = fmaxf(0.25f * a3 + bg[fb + 3], 0.f);
        float r4 = fmaxf(0.25f * a4 + bg[fb + 4], 0.f);
        float r5 = fmaxf(0.25f * a5 + bg[fb + 5], 0.f);
        float r6 = fmaxf(0.25f * a6 + bg[fb + 6], 0.f);
        float r7 = fmaxf(0.25f * a7 + bg[fb + 7], 0.f);
        float* o = g_h + (size_t)n * HID + fb;
        ((float4*)o)[0] = make_float4(r0, r1, r2, r3);
        ((float4*)o)[1] = make_float4(r4, r5, r6, r7);
        union { uint4 u; __half2 h[4]; } pk;
        pk.h[0] = __floats2half2_rn(r0, r1);
        pk.h[1] = __floats2half2_rn(r2, r3);
        pk.h[2] = __floats2half2_rn(r4, r5);
        pk.h[3] = __floats2half2_rn(r6, r7);
        *(uint4*)&g_hh[(size_t)n * HID + fb] = pk.u;
    }
}

// ---------------- global mean pool --------------------------------------------
__global__ void k_pool(const int* __restrict__ batch) {
    __shared__ int s_lo, s_hi;
    __shared__ float red[256];
    int g = blockIdx.x;
    if (threadIdx.x == 0) {
        int lo = 0, hi = NNODES;
        while (lo < hi) { int m = (lo + hi) >> 1; if (batch[m] < g) lo = m + 1; else hi = m; }
        s_lo = lo;
        lo = 0; hi = NNODES;
        while (lo < hi) { int m = (lo + hi) >> 1; if (batch[m] < g + 1) lo = m + 1; else hi = m; }
        s_hi = lo;
    }
    __syncthreads();
    int lo = s_lo, hi = s_hi;
    int f = threadIdx.x & 63, r = threadIdx.x >> 6;
    float acc = 0.f;
    for (int n = lo + r; n < hi; n += 4) acc += g_h[(size_t)n * HID + f];
    red[threadIdx.x] = acc;
    __syncthreads();
    if (threadIdx.x < 64) {
        float v = red[f] + red[64 + f] + red[128 + f] + red[192 + f];
        float cnt = (float)max(hi - lo, 1);
        g_hg[g * HID + f] = v / cnt;
    }
}

// ---------------- final FC (2 outputs per thread) ------------------------------
__global__ void __launch_bounds__(256) k_fc(const float* __restrict__ Wfc,
                                            const float* __restrict__ bfc,
                                            float* __restrict__ out) {
    __shared__ float hg[NG * HID];
    int t = threadIdx.x;
    for (int i = t; i < NG * HID; i += 256) hg[i] = g_hg[i];
    __syncthreads();
    int o2 = blockIdx.x * 256 + t;
    if (o2 >= OUTF / 2) return;
    const float2* W2 = (const float2*)Wfc;
    float2 b2 = ((const float2*)bfc)[o2];
    float acc0[NG], acc1[NG];
    #pragma unroll
    for (int g = 0; g < NG; g++) { acc0[g] = b2.x; acc1[g] = b2.y; }
    for (int f = 0; f < HID; f++) {
        float2 w = W2[(size_t)f * (OUTF / 2) + o2];
        #pragma unroll
        for (int g = 0; g < NG; g++) {
            float hv = hg[g * HID + f];
            acc0[g] = fmaf(hv, w.x, acc0[g]);
            acc1[g] = fmaf(hv, w.y, acc1[g]);
        }
    }
    float2* out2 = (float2*)out;
    #pragma unroll
    for (int g = 0; g < NG; g++)
        out2[(size_t)g * (OUTF / 2) + o2] = make_float2(acc0[g], acc1[g]);
}

// ---------------- launch --------------------------------------------------------
extern "C" void kernel_launch(void* const* d_in, const int* in_sizes, int n_in,
                              void* d_out, int out_size) {
    const float* x     = (const float*)d_in[0];
    const int*   ei    = (const int*)d_in[1];
    const int*   batch = (const int*)d_in[3];
    const float* W_emb = (const float*)d_in[4];
    const float* b_emb = (const float*)d_in[5];
    const float* W_gat = (const float*)d_in[6];
    const float* a_src = (const float*)d_in[7];
    const float* a_dst = (const float*)d_in[8];
    const float* b_gat = (const float*)d_in[9];
    const float* W_fc  = (const float*)d_in[10];
    const float* b_fc  = (const float*)d_in[11];
    float* out = (float*)d_out;

    void* degp = nullptr;
    cudaGetSymbolAddress(&degp, g_deg);
    cudaMemsetAsync(degp, 0, NNODES * sizeof(int));

    // kernel launch #4 = k_z layer 0 (ncu capture window)
    k_xcvt<<<NPAD * 16 / 256, 256>>>(x);
    k_wcvt<<<48, 256>>>(W_gat);
    k_wfuse<<<INF + 1, 256>>>(W_emb, b_emb, W_gat);
    k_z<<<NZBLK, 256>>>(0, a_src, a_dst);
    k_count<<<(NEDGES + 255) / 256, 256>>>(ei);
    k_bsum<<<NBLK, 256>>>();
    k_bscan<<<1, 256>>>();
    k_offsets<<<NBLK, 256>>>();
    k_scatter<<<(NEDGES + 255) / 256, 256>>>(ei);
    k_agg<<<(NNODES * 32 + 255) / 256, 256>>>(b_gat);

    for (int l = 1; l < 3; l++) {
        k_z<<<NZBLK, 256>>>(l,
                            a_src + (size_t)l * HEADS * HID,
                            a_dst + (size_t)l * HEADS * HID);
        k_agg<<<(NNODES * 32 + 255) / 256, 256>>>(b_gat + (size_t)l * HID);
    }

    k_pool<<<NG, 256>>>(batch);
    k_fc<<<(OUTF / 2 + 255) / 256, 256>>>(W_fc, b_fc, out);
}